// round 14
// baseline (speedup 1.0000x reference)
#include <cuda_runtime.h>
#include <cuda_bf16.h>
#include <math.h>
#include <stdint.h>

#define BQ 32
#define NN 2048

// Scratch (device globals; no allocations allowed)
__device__ float g_h1[BQ * NN * 160];
__device__ float g_h2[BQ * NN * 80];
__device__ float g_h3[BQ * NN * 40];
__device__ float g_h4[BQ * NN * 5];
// K in fragment order: [batch][node][ks*4+t] = {hi(b0),lo(b0),hi(b1),lo(b1)}
__device__ uint4 g_kpk1[BQ * NN * 20];          // C2=40 -> 20 uint4/node
__device__ uint4 g_kpk2[BQ * NN * 12];          // C2=24 -> 12 uint4/node
// V in tile+fragment order: [batch][tile][kbp*4+t][col] = {b0,b1} (bf16x2 each)
__device__ uint2 g_vq1[BQ * (NN / 64) * 16 * 40];
__device__ uint2 g_vq2[BQ * (NN / 64) * 16 * 8];
__device__ float g_ksql[BQ * NN];               // |h|^2 * log2(e)

// ---------------------------------------------------------------------------
// helpers
// ---------------------------------------------------------------------------
#define LOG2E_F 1.4426950408889634f
#define C2E_F   2.8853900817779268f   // 2*log2(e)

__device__ __forceinline__ float ex2f(float x) {
    float r;
    asm("ex2.approx.f32 %0, %1;" : "=f"(r) : "f"(x));
    return r;
}

// pack (e -> low16, o -> high16) as bf16x2
__device__ __forceinline__ uint32_t packbf2(float e, float o) {
    uint32_t r;
    asm("cvt.rn.bf16x2.f32 %0, %1, %2;" : "=r"(r) : "f"(o), "f"(e));
    return r;
}

__device__ __forceinline__ void mma_bf16(float c[4], uint32_t a0, uint32_t a1,
                                         uint32_t a2, uint32_t a3,
                                         uint32_t b0, uint32_t b1) {
    asm volatile(
        "mma.sync.aligned.m16n8k16.row.col.f32.bf16.bf16.f32 "
        "{%0,%1,%2,%3}, {%4,%5,%6,%7}, {%8,%9}, {%0,%1,%2,%3};\n"
        : "+f"(c[0]), "+f"(c[1]), "+f"(c[2]), "+f"(c[3])
        : "r"(a0), "r"(a1), "r"(a2), "r"(a3), "r"(b0), "r"(b1));
}

// split (e,o) into bf16 hi pair + bf16 lo (residual) pair
__device__ __forceinline__ void split2(float xe, float xo, uint32_t& hi, uint32_t& lo) {
    float he = __bfloat162float(__float2bfloat16(xe));
    float ho = __bfloat162float(__float2bfloat16(xo));
    hi = packbf2(xe, xo);
    lo = packbf2(xe - he, xo - ho);
}

__device__ __forceinline__ void cp_async16(uint32_t saddr, const void* gptr) {
    asm volatile("cp.async.ca.shared.global [%0], [%1], 16;\n" ::"r"(saddr), "l"(gptr));
}
__device__ __forceinline__ void cp_async8(uint32_t saddr, const void* gptr) {
    asm volatile("cp.async.ca.shared.global [%0], [%1], 8;\n" ::"r"(saddr), "l"(gptr));
}
__device__ __forceinline__ void cp_async4(uint32_t saddr, const void* gptr) {
    asm volatile("cp.async.ca.shared.global [%0], [%1], 4;\n" ::"r"(saddr), "l"(gptr));
}
__device__ __forceinline__ void cp_commit() {
    asm volatile("cp.async.commit_group;\n");
}
__device__ __forceinline__ void cp_wait1() {
    asm volatile("cp.async.wait_group 1;\n");
}

// ---------------------------------------------------------------------------
// MMA GEMM: C[M,N] = relu(A[M,K] @ W[K,N] + b[N]), bf16x2 3-term.
// 256 threads (8 warps), tile 128x64, BK=32.  K % 32 == 0, M % 128 == 0.
// ---------------------------------------------------------------------------
__global__ void gemm_mma_relu_kernel(const float* __restrict__ A,
                                     const float* __restrict__ W,
                                     const float* __restrict__ bias,
                                     float* __restrict__ C,
                                     int M, int K, int N) {
    constexpr int KP = 20;  // uint2 per row (16 used; 20 % 8 == 4 -> conflict-free)
    __shared__ uint2 Asm[128 * KP];
    __shared__ uint2 Wsm[64 * KP];

    const int tid = threadIdx.x;
    const int lane = tid & 31, warp = tid >> 5;
    const int g = lane >> 2, t = lane & 3;
    const int m0 = blockIdx.y * 128, n0 = blockIdx.x * 64;
    const int row0 = warp * 16 + g;

    float acc[8][4];
    #pragma unroll
    for (int f = 0; f < 8; f++)
        acc[f][0] = acc[f][1] = acc[f][2] = acc[f][3] = 0.0f;

    for (int k0 = 0; k0 < K; k0 += 32) {
        #pragma unroll
        for (int i = 0; i < 8; i++) {
            int idx = tid + i * 256;
            int r = idx >> 4, c2 = idx & 15;
            float2 av = *(const float2*)&A[(size_t)(m0 + r) * K + k0 + 2 * c2];
            uint32_t hi, lo;
            split2(av.x, av.y, hi, lo);
            Asm[r * KP + c2] = make_uint2(hi, lo);
        }
        #pragma unroll
        for (int i = 0; i < 4; i++) {
            int idx = tid + i * 256;
            int c2 = idx >> 6, n = idx & 63;
            float we = 0.0f, wo = 0.0f;
            if (n0 + n < N) {
                we = W[(size_t)(k0 + 2 * c2) * N + n0 + n];
                wo = W[(size_t)(k0 + 2 * c2 + 1) * N + n0 + n];
            }
            uint32_t hi, lo;
            split2(we, wo, hi, lo);
            Wsm[n * KP + c2] = make_uint2(hi, lo);
        }
        __syncthreads();

        #pragma unroll
        for (int ks = 0; ks < 16; ks += 8) {
            uint2 a0 = Asm[row0 * KP + ks + t];
            uint2 a1 = Asm[(row0 + 8) * KP + ks + t];
            uint2 a2 = Asm[row0 * KP + ks + t + 4];
            uint2 a3 = Asm[(row0 + 8) * KP + ks + t + 4];
            #pragma unroll
            for (int f = 0; f < 8; f++) {
                uint2 b0 = Wsm[(8 * f + g) * KP + ks + t];
                uint2 b1 = Wsm[(8 * f + g) * KP + ks + t + 4];
                mma_bf16(acc[f], a0.x, a1.x, a2.x, a3.x, b0.y, b1.y);  // ah*bl
                mma_bf16(acc[f], a0.y, a1.y, a2.y, a3.y, b0.x, b1.x);  // al*bh
                mma_bf16(acc[f], a0.x, a1.x, a2.x, a3.x, b0.x, b1.x);  // ah*bh
            }
        }
        __syncthreads();
    }

    #pragma unroll
    for (int f = 0; f < 8; f++) {
        int c0 = n0 + 8 * f + 2 * t, c1 = c0 + 1;
        if (c0 < N) {
            float bv = bias[c0];
            C[(size_t)(m0 + row0) * N + c0] = fmaxf(acc[f][0] + bv, 0.0f);
            C[(size_t)(m0 + row0 + 8) * N + c0] = fmaxf(acc[f][2] + bv, 0.0f);
        }
        if (c1 < N) {
            float bv = bias[c1];
            C[(size_t)(m0 + row0) * N + c1] = fmaxf(acc[f][1] + bv, 0.0f);
            C[(size_t)(m0 + row0 + 8) * N + c1] = fmaxf(acc[f][3] + bv, 0.0f);
        }
    }
}

// ---------------------------------------------------------------------------
// Prep per graph-conv layer (same as R10/R13).
// ---------------------------------------------------------------------------
template <int C, int C2, int COUT, int VN>
__global__ void gc_prep_kernel(const float* __restrict__ H,
                               const float* __restrict__ Wg,
                               uint4* __restrict__ Kpk4,
                               uint2* __restrict__ Vq,
                               float* __restrict__ ksql_g) {
    constexpr int KW4 = C2 / 2;   // uint4 per node
    __shared__ float Hs[64][C + 1];
    __shared__ float Wgs[C * COUT];
    __shared__ float Vsf[64 * VN];
    const int tid = threadIdx.x;
    const int batch = blockIdx.y;
    const int n0 = blockIdx.x * 64;
    const float* Hb = H + (size_t)batch * NN * C + (size_t)n0 * C;

    for (int idx = tid; idx < 64 * C; idx += 256) {
        Hs[idx / C][idx % C] = Hb[idx];
    }
    for (int idx = tid; idx < C * COUT; idx += 256) Wgs[idx] = Wg[idx];
    __syncthreads();

    uint4* Kb = Kpk4 + (size_t)(batch * NN + n0) * KW4;
    for (int idx = tid; idx < 64 * KW4; idx += 256) {
        int r = idx / KW4, w = idx % KW4;
        int ks = w >> 2, t = w & 3;
        int c2a = 8 * ks + t, c2b = c2a + 4;
        float e0 = (2 * c2a < C) ? Hs[r][2 * c2a] : 0.0f;
        float o0 = (2 * c2a + 1 < C) ? Hs[r][2 * c2a + 1] : 0.0f;
        float e1 = (2 * c2b < C) ? Hs[r][2 * c2b] : 0.0f;
        float o1 = (2 * c2b + 1 < C) ? Hs[r][2 * c2b + 1] : 0.0f;
        uint32_t h0, l0, h1, l1;
        split2(e0, o0, h0, l0);
        split2(e1, o1, h1, l1);
        Kb[idx] = make_uint4(h0, l0, h1, l1);
    }
    if (tid < 64) {
        float s = 0.0f;
        #pragma unroll 4
        for (int c = 0; c < C; c++) { float v = Hs[tid][c]; s += v * v; }
        ksql_g[(size_t)batch * NN + n0 + tid] = s * LOG2E_F;
    }
    for (int idx = tid; idx < 64 * VN; idx += 256) {
        int r = idx / VN, o = idx % VN;
        float v = 0.0f;
        if (o < COUT) {
            #pragma unroll 4
            for (int c = 0; c < C; c++) v += Hs[r][c] * Wgs[c * COUT + o];
        }
        Vsf[r * VN + o] = v;
    }
    __syncthreads();
    uint2* Vb = Vq + (size_t)(batch * (NN / 64) + blockIdx.x) * 16 * VN;
    for (int idx = tid; idx < 16 * VN; idx += 256) {
        int w = idx / VN, c = idx % VN;
        int r0 = (w >> 2) * 8 + (w & 3);   // keypair row in tile
        int r1 = r0 + 4;
        Vb[idx] = make_uint2(
            packbf2(Vsf[(2 * r0) * VN + c], Vsf[(2 * r0 + 1) * VN + c]),
            packbf2(Vsf[(2 * r1) * VN + c], Vsf[(2 * r1 + 1) * VN + c]));
    }
}

// ---------------------------------------------------------------------------
// Wide attention kernel: 128 threads = 4 warps, each warp owns 32 query rows
// (two m16 row-blocks) -> 128 query rows per block.  Per tile the 8 key
// blocks are processed in TWO HALVES of 4 (8 independent MMA chains each) so
// live S registers drop 64 -> 32 and 3 blocks/SM fit (launch_bounds(128,3)).
// Accumulation order (j = 0..7 for l, kbp = 0..3 for acc) matches R13 exactly.
// ---------------------------------------------------------------------------
template <int C2, int COUT, int VN, int VP>
__global__ __launch_bounds__(128, 3)
void gc_attn128_kernel(const uint4* __restrict__ Kpk4,
                       const float* __restrict__ ksql_g,
                       const uint2* __restrict__ Vq,
                       const float* __restrict__ bg,
                       float* __restrict__ Out) {
    static_assert(C2 % 8 == 0, "");
    constexpr int KS16 = C2 / 8;
    constexpr int KW4 = C2 / 2;
    constexpr int NT = VN / 8;
    constexpr int KI = 64 * KW4 / 128;
    constexpr int VI = (16 * VN + 127) / 128;
    constexpr int KBUF = 64 * KW4;
    constexpr int VBUF = 16 * VP;
    constexpr int NTILE = NN / 64;

    extern __shared__ char smraw[];
    uint4* Ks = (uint4*)smraw;                       // [2][KBUF]
    uint2* Vs = (uint2*)(Ks + 2 * KBUF);             // [2][VBUF]
    float* ksqs = (float*)(Vs + 2 * VBUF);           // [2][64]

    const int tid = threadIdx.x;
    const int lane = tid & 31, warp = tid >> 5;
    const int g = lane >> 2, t = lane & 3;
    const int batch = blockIdx.y;
    const int q0 = blockIdx.x * 128;
    const uint4* Kg = Kpk4 + (size_t)batch * NN * KW4;
    const uint2* Vg = Vq + (size_t)batch * (NN / 64) * 16 * VN;
    const float* ksqlb = ksql_g + (size_t)batch * NN;

    const int row0 = warp * 32 + g;   // rows row0, +8 (block A), +16, +24 (block B)

    // ---- Q fragments in registers (fragment order) ----
    uint4 qA0[KS16], qA1[KS16], qB0[KS16], qB1[KS16];
    {
        const uint4* Q0 = Kg + (size_t)(q0 + row0) * KW4;
        const uint4* Q1 = Kg + (size_t)(q0 + row0 + 8) * KW4;
        const uint4* Q2 = Kg + (size_t)(q0 + row0 + 16) * KW4;
        const uint4* Q3 = Kg + (size_t)(q0 + row0 + 24) * KW4;
        #pragma unroll
        for (int ks = 0; ks < KS16; ks++) {
            qA0[ks] = Q0[ks * 4 + t];
            qA1[ks] = Q1[ks * 4 + t];
            qB0[ks] = Q2[ks * 4 + t];
            qB1[ks] = Q3[ks * 4 + t];
        }
    }
    const float ql0 = ksqlb[q0 + row0];
    const float ql1 = ksqlb[q0 + row0 + 8];
    const float ql2 = ksqlb[q0 + row0 + 16];
    const float ql3 = ksqlb[q0 + row0 + 24];

    const uint32_t ks_s = (uint32_t)__cvta_generic_to_shared(Ks);
    const uint32_t vs_s = (uint32_t)__cvta_generic_to_shared(Vs);
    const uint32_t kq_s = (uint32_t)__cvta_generic_to_shared(ksqs);

    #define PREFETCH(tile_, buf_)                                              \
    do {                                                                       \
        const int kk0 = (tile_)*64;                                            \
        _Pragma("unroll")                                                      \
        for (int i = 0; i < KI; i++) {                                         \
            int idx = tid + i * 128;                                           \
            cp_async16(ks_s + ((buf_)*KBUF + idx) * 16,                        \
                       &Kg[(size_t)kk0 * KW4 + idx]);                          \
        }                                                                      \
        _Pragma("unroll")                                                      \
        for (int i = 0; i < VI; i++) {                                         \
            int idx = tid + i * 128;                                           \
            if (idx < 16 * VN) {                                               \
                int w = idx / VN, c = idx % VN;                                \
                cp_async8(vs_s + ((buf_)*VBUF + w * VP + c) * 8,               \
                          &Vg[(size_t)(tile_)*16 * VN + idx]);                 \
            }                                                                  \
        }                                                                      \
        if (tid < 64)                                                          \
            cp_async4(kq_s + ((buf_)*64 + tid) * 4, &ksqlb[kk0 + tid]);        \
    } while (0)

    PREFETCH(0, 0);
    cp_commit();

    float accA[NT][4], accB[NT][4];
    #pragma unroll
    for (int j = 0; j < NT; j++) {
        accA[j][0] = accA[j][1] = accA[j][2] = accA[j][3] = 0.0f;
        accB[j][0] = accB[j][1] = accB[j][2] = accB[j][3] = 0.0f;
    }
    float lA0 = 0.0f, lA1 = 0.0f, lB0 = 0.0f, lB1 = 0.0f;

    for (int tile = 0; tile < NTILE; tile++) {
        const int buf = tile & 1;
        if (tile + 1 < NTILE) PREFETCH(tile + 1, buf ^ 1);
        cp_commit();
        cp_wait1();
        __syncthreads();

        const uint4* Kb = Ks + buf * KBUF;
        const uint2* Vt = Vs + buf * VBUF;
        const float* kqt = ksqs + buf * 64;

        // ---- two halves of 4 key-blocks each (8 indep chains per half) ----
        #pragma unroll
        for (int half = 0; half < 2; half++) {
            float sA[4][4], sB[4][4];
            #pragma unroll
            for (int jj = 0; jj < 4; jj++) {
                sA[jj][0] = sA[jj][1] = sA[jj][2] = sA[jj][3] = 0.0f;
                sB[jj][0] = sB[jj][1] = sB[jj][2] = sB[jj][3] = 0.0f;
            }
            #pragma unroll
            for (int ks = 0; ks < KS16; ks++) {
                #pragma unroll
                for (int jj = 0; jj < 4; jj++) {
                    const int j = 4 * half + jj;
                    uint4 kb = Kb[(8 * j + g) * KW4 + ks * 4 + t];
                    mma_bf16(sA[jj], qA0[ks].x, qA1[ks].x, qA0[ks].z, qA1[ks].z, kb.y, kb.w);
                    mma_bf16(sA[jj], qA0[ks].y, qA1[ks].y, qA0[ks].w, qA1[ks].w, kb.x, kb.z);
                    mma_bf16(sA[jj], qA0[ks].x, qA1[ks].x, qA0[ks].z, qA1[ks].z, kb.x, kb.z);
                    mma_bf16(sB[jj], qB0[ks].x, qB1[ks].x, qB0[ks].z, qB1[ks].z, kb.y, kb.w);
                    mma_bf16(sB[jj], qB0[ks].y, qB1[ks].y, qB0[ks].w, qB1[ks].w, kb.x, kb.z);
                    mma_bf16(sB[jj], qB0[ks].x, qB1[ks].x, qB0[ks].z, qB1[ks].z, kb.x, kb.z);
                }
            }

            uint2 pkA[4], pkB[4];
            #pragma unroll
            for (int jj = 0; jj < 4; jj++) {
                const int j = 4 * half + jj;
                float kl0 = kqt[8 * j + 2 * t], kl1 = kqt[8 * j + 2 * t + 1];
                float a00 = ex2f(fmaf(sA[jj][0], C2E_F, -(kl0 + ql0)));
                float a01 = ex2f(fmaf(sA[jj][1], C2E_F, -(kl1 + ql0)));
                float a02 = ex2f(fmaf(sA[jj][2], C2E_F, -(kl0 + ql1)));
                float a03 = ex2f(fmaf(sA[jj][3], C2E_F, -(kl1 + ql1)));
                lA0 += a00 + a01;
                lA1 += a02 + a03;
                pkA[jj] = make_uint2(packbf2(a00, a01), packbf2(a02, a03));
                float b00 = ex2f(fmaf(sB[jj][0], C2E_F, -(kl0 + ql2)));
                float b01 = ex2f(fmaf(sB[jj][1], C2E_F, -(kl1 + ql2)));
                float b02 = ex2f(fmaf(sB[jj][2], C2E_F, -(kl0 + ql3)));
                float b03 = ex2f(fmaf(sB[jj][3], C2E_F, -(kl1 + ql3)));
                lB0 += b00 + b01;
                lB1 += b02 + b03;
                pkB[jj] = make_uint2(packbf2(b00, b01), packbf2(b02, b03));
            }

            #pragma unroll
            for (int kk = 0; kk < 2; kk++) {
                const int kbp = 2 * half + kk;
                uint32_t aA0 = pkA[2 * kk].x, aA1 = pkA[2 * kk].y;
                uint32_t aA2 = pkA[2 * kk + 1].x, aA3 = pkA[2 * kk + 1].y;
                uint32_t aB0 = pkB[2 * kk].x, aB1 = pkB[2 * kk].y;
                uint32_t aB2 = pkB[2 * kk + 1].x, aB3 = pkB[2 * kk + 1].y;
                #pragma unroll
                for (int jj = 0; jj < NT; jj++) {
                    uint2 vv = Vt[(kbp * 4 + t) * VP + 8 * jj + g];
                    mma_bf16(accA[jj], aA0, aA1, aA2, aA3, vv.x, vv.y);
                    mma_bf16(accB[jj], aB0, aB1, aB2, aB3, vv.x, vv.y);
                }
            }
        }
        __syncthreads();
    }
    #undef PREFETCH

    // ---- epilogue ----
    lA0 += __shfl_xor_sync(0xffffffffu, lA0, 1);
    lA0 += __shfl_xor_sync(0xffffffffu, lA0, 2);
    lA1 += __shfl_xor_sync(0xffffffffu, lA1, 1);
    lA1 += __shfl_xor_sync(0xffffffffu, lA1, 2);
    lB0 += __shfl_xor_sync(0xffffffffu, lB0, 1);
    lB0 += __shfl_xor_sync(0xffffffffu, lB0, 2);
    lB1 += __shfl_xor_sync(0xffffffffu, lB1, 1);
    lB1 += __shfl_xor_sync(0xffffffffu, lB1, 2);
    float iA0 = 1.0f / lA0, iA1 = 1.0f / lA1;
    float iB0 = 1.0f / lB0, iB1 = 1.0f / lB1;
    float* Outb = Out + (size_t)batch * NN * COUT + (size_t)q0 * COUT;
    #pragma unroll
    for (int j = 0; j < NT; j++) {
        int c0 = 8 * j + 2 * t, c1 = c0 + 1;
        if (c0 < COUT) {
            float bv = __ldg(&bg[c0]);
            Outb[row0 * COUT + c0] = fmaxf(accA[j][0] * iA0 + bv, 0.0f);
            Outb[(row0 + 8) * COUT + c0] = fmaxf(accA[j][2] * iA1 + bv, 0.0f);
            Outb[(row0 + 16) * COUT + c0] = fmaxf(accB[j][0] * iB0 + bv, 0.0f);
            Outb[(row0 + 24) * COUT + c0] = fmaxf(accB[j][2] * iB1 + bv, 0.0f);
        }
        if (c1 < COUT) {
            float bv = __ldg(&bg[c1]);
            Outb[row0 * COUT + c1] = fmaxf(accA[j][1] * iA0 + bv, 0.0f);
            Outb[(row0 + 8) * COUT + c1] = fmaxf(accA[j][3] * iA1 + bv, 0.0f);
            Outb[(row0 + 16) * COUT + c1] = fmaxf(accB[j][1] * iB0 + bv, 0.0f);
            Outb[(row0 + 24) * COUT + c1] = fmaxf(accB[j][3] * iB1 + bv, 0.0f);
        }
    }
}

// ---------------------------------------------------------------------------
// R10 attention kernel (64 query rows, 16/warp) -- used for layer 2.
// ---------------------------------------------------------------------------
template <int C2, int COUT, int VN, int VP>
__global__ __launch_bounds__(128, 4)
void gc_attn_kernel(const uint4* __restrict__ Kpk4,
                    const float* __restrict__ ksql_g,
                    const uint2* __restrict__ Vq,
                    const float* __restrict__ bg,
                    float* __restrict__ Out) {
    static_assert(C2 % 8 == 0, "");
    constexpr int KS16 = C2 / 8;
    constexpr int KW4 = C2 / 2;
    constexpr int NT = VN / 8;
    constexpr int KI = 64 * KW4 / 128;
    constexpr int VI = (16 * VN + 127) / 128;
    constexpr int KBUF = 64 * KW4;
    constexpr int VBUF = 16 * VP;
    constexpr int NTILE = NN / 64;

    extern __shared__ char smraw[];
    uint4* Ks = (uint4*)smraw;
    uint2* Vs = (uint2*)(Ks + 2 * KBUF);
    float* ksqs = (float*)(Vs + 2 * VBUF);

    const int tid = threadIdx.x;
    const int lane = tid & 31, warp = tid >> 5;
    const int g = lane >> 2, t = lane & 3;
    const int batch = blockIdx.y;
    const int q0 = blockIdx.x * 64;
    const uint4* Kg = Kpk4 + (size_t)batch * NN * KW4;
    const uint2* Vg = Vq + (size_t)batch * (NN / 64) * 16 * VN;
    const float* ksqlb = ksql_g + (size_t)batch * NN;

    const int row0 = warp * 16 + g;

    uint4 qr0[KS16], qr1[KS16];
    {
        const uint4* Q0 = Kg + (size_t)(q0 + row0) * KW4;
        const uint4* Q1 = Kg + (size_t)(q0 + row0 + 8) * KW4;
        #pragma unroll
        for (int ks = 0; ks < KS16; ks++) {
            qr0[ks] = Q0[ks * 4 + t];
            qr1[ks] = Q1[ks * 4 + t];
        }
    }
    const float ql0 = ksqlb[q0 + row0];
    const float ql1 = ksqlb[q0 + row0 + 8];

    const uint32_t ks_s = (uint32_t)__cvta_generic_to_shared(Ks);
    const uint32_t vs_s = (uint32_t)__cvta_generic_to_shared(Vs);
    const uint32_t kq_s = (uint32_t)__cvta_generic_to_shared(ksqs);

    #define PREFETCH(tile_, buf_)                                              \
    do {                                                                       \
        const int kk0 = (tile_)*64;                                            \
        _Pragma("unroll")                                                      \
        for (int i = 0; i < KI; i++) {                                         \
            int idx = tid + i * 128;                                           \
            cp_async16(ks_s + ((buf_)*KBUF + idx) * 16,                        \
                       &Kg[(size_t)kk0 * KW4 + idx]);                          \
        }                                                                      \
        _Pragma("unroll")                                                      \
        for (int i = 0; i < VI; i++) {                                         \
            int idx = tid + i * 128;                                           \
            if (idx < 16 * VN) {                                               \
                int w = idx / VN, c = idx % VN;                                \
                cp_async8(vs_s + ((buf_)*VBUF + w * VP + c) * 8,               \
                          &Vg[(size_t)(tile_)*16 * VN + idx]);                 \
            }                                                                  \
        }                                                                      \
        if (tid < 64)                                                          \
            cp_async4(kq_s + ((buf_)*64 + tid) * 4, &ksqlb[kk0 + tid]);        \
    } while (0)

    PREFETCH(0, 0);
    cp_commit();

    float acc[NT][4];
    #pragma unroll
    for (int j = 0; j < NT; j++)
        acc[j][0] = acc[j][1] = acc[j][2] = acc[j][3] = 0.0f;
    float l0r = 0.0f, l1r = 0.0f;

    for (int tile = 0; tile < NTILE; tile++) {
        const int buf = tile & 1;
        if (tile + 1 < NTILE) PREFETCH(tile + 1, buf ^ 1);
        cp_commit();
        cp_wait1();
        __syncthreads();

        const uint4* Kb = Ks + buf * KBUF;
        const uint2* Vt = Vs + buf * VBUF;
        const float* kqt = ksqs + buf * 64;

        float s[8][4];
        #pragma unroll
        for (int j = 0; j < 8; j++) s[j][0] = s[j][1] = s[j][2] = s[j][3] = 0.0f;

        #pragma unroll
        for (int ks = 0; ks < KS16; ks++) {
            #pragma unroll
            for (int j = 0; j < 8; j++) {
                uint4 kb = Kb[(8 * j + g) * KW4 + ks * 4 + t];
                mma_bf16(s[j], qr0[ks].x, qr1[ks].x, qr0[ks].z, qr1[ks].z, kb.y, kb.w);
                mma_bf16(s[j], qr0[ks].y, qr1[ks].y, qr0[ks].w, qr1[ks].w, kb.x, kb.z);
                mma_bf16(s[j], qr0[ks].x, qr1[ks].x, qr0[ks].z, qr1[ks].z, kb.x, kb.z);
            }
        }

        uint32_t pA[8], pB[8];
        #pragma unroll
        for (int j = 0; j < 8; j++) {
            float kl0 = kqt[8 * j + 2 * t], kl1 = kqt[8 * j + 2 * t + 1];
            float p00 = ex2f(fmaf(s[j][0], C2E_F, -(kl0 + ql0)));
            float p01 = ex2f(fmaf(s[j][1], C2E_F, -(kl1 + ql0)));
            float p10 = ex2f(fmaf(s[j][2], C2E_F, -(kl0 + ql1)));
            float p11 = ex2f(fmaf(s[j][3], C2E_F, -(kl1 + ql1)));
            l0r += p00 + p01;
            l1r += p10 + p11;
            pA[j] = packbf2(p00, p01);
            pB[j] = packbf2(p10, p11);
        }

        #pragma unroll
        for (int kbp = 0; kbp < 4; kbp++) {
            uint32_t a0 = pA[2 * kbp], a1 = pB[2 * kbp];
            uint32_t a2 = pA[2 * kbp + 1], a3 = pB[2 * kbp + 1];
            #pragma unroll
            for (int jj = 0; jj < NT; jj++) {
                uint2 vv = Vt[(kbp * 4 + t) * VP + 8 * jj + g];
                mma_bf16(acc[jj], a0, a1, a2, a3, vv.x, vv.y);
            }
        }
        __syncthreads();
    }
    #undef PREFETCH

    l0r += __shfl_xor_sync(0xffffffffu, l0r, 1);
    l0r += __shfl_xor_sync(0xffffffffu, l0r, 2);
    l1r += __shfl_xor_sync(0xffffffffu, l1r, 1);
    l1r += __shfl_xor_sync(0xffffffffu, l1r, 2);
    float inv0 = 1.0f / l0r, inv1 = 1.0f / l1r;
    float* Outb = Out + (size_t)batch * NN * COUT + (size_t)q0 * COUT;
    #pragma unroll
    for (int j = 0; j < NT; j++) {
        int c0 = 8 * j + 2 * t, c1 = c0 + 1;
        if (c0 < COUT) {
            float b0v = __ldg(&bg[c0]);
            Outb[row0 * COUT + c0] = fmaxf(acc[j][0] * inv0 + b0v, 0.0f);
            Outb[(row0 + 8) * COUT + c0] = fmaxf(acc[j][2] * inv1 + b0v, 0.0f);
        }
        if (c1 < COUT) {
            float b1v = __ldg(&bg[c1]);
            Outb[row0 * COUT + c1] = fmaxf(acc[j][1] * inv0 + b1v, 0.0f);
            Outb[(row0 + 8) * COUT + c1] = fmaxf(acc[j][3] * inv1 + b1v, 0.0f);
        }
    }
}

// ---------------------------------------------------------------------------
// Mean over nodes -> classifier -> softmax. One block per batch.
// ---------------------------------------------------------------------------
__global__ void finalize_kernel(const float* __restrict__ H4,
                                const float* __restrict__ Wf,
                                const float* __restrict__ bf,
                                float* __restrict__ out) {
    int b = blockIdx.x;
    int tid = threadIdx.x;
    __shared__ float sred[5][256];
    float local[5] = {};
    const float* Hb = H4 + (long)b * NN * 5;
    for (int r = tid; r < NN; r += 256) {
        #pragma unroll
        for (int c = 0; c < 5; c++) local[c] += Hb[r * 5 + c];
    }
    #pragma unroll
    for (int c = 0; c < 5; c++) sred[c][tid] = local[c];
    __syncthreads();
    for (int s = 128; s > 0; s >>= 1) {
        if (tid < s) {
            #pragma unroll
            for (int c = 0; c < 5; c++) sred[c][tid] += sred[c][tid + s];
        }
        __syncthreads();
    }
    if (tid == 0) {
        float mean[5];
        #pragma unroll
        for (int c = 0; c < 5; c++) mean[c] = sred[c][0] / (float)NN;
        float lg[2];
        #pragma unroll
        for (int o = 0; o < 2; o++) {
            float v = bf[o];
            #pragma unroll
            for (int c = 0; c < 5; c++) v += mean[c] * Wf[c * 2 + o];
            lg[o] = v;
        }
        float mx = fmaxf(lg[0], lg[1]);
        float e0 = expf(lg[0] - mx), e1 = expf(lg[1] - mx);
        float inv = 1.0f / (e0 + e1);
        out[b * 2 + 0] = e0 * inv;
        out[b * 2 + 1] = e1 * inv;
    }
}

// ---------------------------------------------------------------------------

static size_t attn_smem_bytes(int C2, int VP) {
    int kw4 = C2 / 2;
    return (size_t)2 * 64 * kw4 * 16 + (size_t)2 * 16 * VP * 8 + 2 * 64 * 4;
}

extern "C" void kernel_launch(void* const* d_in, const int* in_sizes, int n_in,
                              void* d_out, int out_size) {
    const float* x   = (const float*)d_in[0];
    const float* W1  = (const float*)d_in[1];
    const float* b1  = (const float*)d_in[2];
    const float* W2  = (const float*)d_in[3];
    const float* b2  = (const float*)d_in[4];
    const float* Wg1 = (const float*)d_in[5];
    const float* bg1 = (const float*)d_in[6];
    const float* Wg2 = (const float*)d_in[7];
    const float* bg2 = (const float*)d_in[8];
    const float* Wf  = (const float*)d_in[9];
    const float* bf  = (const float*)d_in[10];
    float* out = (float*)d_out;

    float *h1, *h2, *h3, *h4, *ksql;
    uint4 *k1, *k2;
    uint2 *v1, *v2;
    cudaGetSymbolAddress((void**)&h1, g_h1);
    cudaGetSymbolAddress((void**)&h2, g_h2);
    cudaGetSymbolAddress((void**)&h3, g_h3);
    cudaGetSymbolAddress((void**)&h4, g_h4);
    cudaGetSymbolAddress((void**)&k1, g_kpk1);
    cudaGetSymbolAddress((void**)&k2, g_kpk2);
    cudaGetSymbolAddress((void**)&v1, g_vq1);
    cudaGetSymbolAddress((void**)&v2, g_vq2);
    cudaGetSymbolAddress((void**)&ksql, g_ksql);

    size_t smem1 = attn_smem_bytes(40, 44);
    size_t smem2 = attn_smem_bytes(24, 12);
    cudaFuncSetAttribute(gc_attn128_kernel<40, 40, 40, 44>,
                         cudaFuncAttributeMaxDynamicSharedMemorySize, (int)smem1);
    cudaFuncSetAttribute(gc_attn_kernel<24, 5, 8, 12>,
                         cudaFuncAttributeMaxDynamicSharedMemorySize, (int)smem2);

    const int M = BQ * NN;  // 65536
    dim3 gprep(NN / 64, BQ);

    gemm_mma_relu_kernel<<<dim3(3, M / 128), 256>>>(x, W1, b1, h1, M, 320, 160);
    gemm_mma_relu_kernel<<<dim3(2, M / 128), 256>>>(h1, W2, b2, h2, M, 160, 80);

    gc_prep_kernel<80, 40, 40, 40><<<gprep, 256>>>(h2, Wg1, k1, v1, ksql);
    gc_attn128_kernel<40, 40, 40, 44><<<dim3(NN / 128, BQ), 128, smem1>>>(
        k1, ksql, v1, bg1, h3);

    gc_prep_kernel<40, 24, 5, 8><<<gprep, 256>>>(h3, Wg2, k2, v2, ksql);
    gc_attn_kernel<24, 5, 8, 12><<<dim3(NN / 64, BQ), 128, smem2>>>(
        k2, ksql, v2, bg2, h4);

    finalize_kernel<<<BQ, 256>>>(h4, Wf, bf, out);
}

// round 15
// speedup vs baseline: 1.0648x; 1.0648x over previous
#include <cuda_runtime.h>
#include <cuda_bf16.h>
#include <math.h>
#include <stdint.h>

#define BQ 32
#define NN 2048

// Scratch (device globals; no allocations allowed)
__device__ float g_h1[BQ * NN * 160];
__device__ float g_h2[BQ * NN * 80];
__device__ float g_h3[BQ * NN * 40];
__device__ float g_h4[BQ * NN * 5];
// K in fragment order: [batch][node][ks*4+t] = {hi(b0),lo(b0),hi(b1),lo(b1)}
__device__ uint4 g_kpk1[BQ * NN * 20];          // C2=40 -> 20 uint4/node
__device__ uint4 g_kpk2[BQ * NN * 12];          // C2=24 -> 12 uint4/node
// V in tile+fragment order: [batch][tile][kbp*4+t][col] = {b0,b1} (bf16x2 each)
__device__ uint2 g_vq1[BQ * (NN / 64) * 16 * 40];
__device__ uint2 g_vq2[BQ * (NN / 64) * 16 * 8];
__device__ float g_ksql[BQ * NN];               // |h|^2 * log2(e)

// ---------------------------------------------------------------------------
// helpers
// ---------------------------------------------------------------------------
#define LOG2E_F 1.4426950408889634f
#define C2E_F   2.8853900817779268f   // 2*log2(e)

__device__ __forceinline__ float ex2f(float x) {
    float r;
    asm("ex2.approx.f32 %0, %1;" : "=f"(r) : "f"(x));
    return r;
}

// pack (e -> low16, o -> high16) as bf16x2
__device__ __forceinline__ uint32_t packbf2(float e, float o) {
    uint32_t r;
    asm("cvt.rn.bf16x2.f32 %0, %1, %2;" : "=r"(r) : "f"(o), "f"(e));
    return r;
}

__device__ __forceinline__ void mma_bf16(float c[4], uint32_t a0, uint32_t a1,
                                         uint32_t a2, uint32_t a3,
                                         uint32_t b0, uint32_t b1) {
    asm volatile(
        "mma.sync.aligned.m16n8k16.row.col.f32.bf16.bf16.f32 "
        "{%0,%1,%2,%3}, {%4,%5,%6,%7}, {%8,%9}, {%0,%1,%2,%3};\n"
        : "+f"(c[0]), "+f"(c[1]), "+f"(c[2]), "+f"(c[3])
        : "r"(a0), "r"(a1), "r"(a2), "r"(a3), "r"(b0), "r"(b1));
}

// split (e,o) into bf16 hi pair + bf16 lo (residual) pair
__device__ __forceinline__ void split2(float xe, float xo, uint32_t& hi, uint32_t& lo) {
    float he = __bfloat162float(__float2bfloat16(xe));
    float ho = __bfloat162float(__float2bfloat16(xo));
    hi = packbf2(xe, xo);
    lo = packbf2(xe - he, xo - ho);
}

__device__ __forceinline__ void cp_async16(uint32_t saddr, const void* gptr) {
    asm volatile("cp.async.ca.shared.global [%0], [%1], 16;\n" ::"r"(saddr), "l"(gptr));
}
__device__ __forceinline__ void cp_async8(uint32_t saddr, const void* gptr) {
    asm volatile("cp.async.ca.shared.global [%0], [%1], 8;\n" ::"r"(saddr), "l"(gptr));
}
__device__ __forceinline__ void cp_async4(uint32_t saddr, const void* gptr) {
    asm volatile("cp.async.ca.shared.global [%0], [%1], 4;\n" ::"r"(saddr), "l"(gptr));
}
__device__ __forceinline__ void cp_commit() {
    asm volatile("cp.async.commit_group;\n");
}
__device__ __forceinline__ void cp_wait1() {
    asm volatile("cp.async.wait_group 1;\n");
}

// ---------------------------------------------------------------------------
// MMA GEMM: C[M,N] = relu(A[M,K] @ W[K,N] + b[N]), bf16x2 3-term.
// 256 threads (8 warps), tile 128x64, BK=32.  K % 32 == 0, M % 128 == 0.
// ---------------------------------------------------------------------------
__global__ void gemm_mma_relu_kernel(const float* __restrict__ A,
                                     const float* __restrict__ W,
                                     const float* __restrict__ bias,
                                     float* __restrict__ C,
                                     int M, int K, int N) {
    constexpr int KP = 20;  // uint2 per row (16 used; 20 % 8 == 4 -> conflict-free)
    __shared__ uint2 Asm[128 * KP];
    __shared__ uint2 Wsm[64 * KP];

    const int tid = threadIdx.x;
    const int lane = tid & 31, warp = tid >> 5;
    const int g = lane >> 2, t = lane & 3;
    const int m0 = blockIdx.y * 128, n0 = blockIdx.x * 64;
    const int row0 = warp * 16 + g;

    float acc[8][4];
    #pragma unroll
    for (int f = 0; f < 8; f++)
        acc[f][0] = acc[f][1] = acc[f][2] = acc[f][3] = 0.0f;

    for (int k0 = 0; k0 < K; k0 += 32) {
        #pragma unroll
        for (int i = 0; i < 8; i++) {
            int idx = tid + i * 256;
            int r = idx >> 4, c2 = idx & 15;
            float2 av = *(const float2*)&A[(size_t)(m0 + r) * K + k0 + 2 * c2];
            uint32_t hi, lo;
            split2(av.x, av.y, hi, lo);
            Asm[r * KP + c2] = make_uint2(hi, lo);
        }
        #pragma unroll
        for (int i = 0; i < 4; i++) {
            int idx = tid + i * 256;
            int c2 = idx >> 6, n = idx & 63;
            float we = 0.0f, wo = 0.0f;
            if (n0 + n < N) {
                we = W[(size_t)(k0 + 2 * c2) * N + n0 + n];
                wo = W[(size_t)(k0 + 2 * c2 + 1) * N + n0 + n];
            }
            uint32_t hi, lo;
            split2(we, wo, hi, lo);
            Wsm[n * KP + c2] = make_uint2(hi, lo);
        }
        __syncthreads();

        #pragma unroll
        for (int ks = 0; ks < 16; ks += 8) {
            uint2 a0 = Asm[row0 * KP + ks + t];
            uint2 a1 = Asm[(row0 + 8) * KP + ks + t];
            uint2 a2 = Asm[row0 * KP + ks + t + 4];
            uint2 a3 = Asm[(row0 + 8) * KP + ks + t + 4];
            #pragma unroll
            for (int f = 0; f < 8; f++) {
                uint2 b0 = Wsm[(8 * f + g) * KP + ks + t];
                uint2 b1 = Wsm[(8 * f + g) * KP + ks + t + 4];
                mma_bf16(acc[f], a0.x, a1.x, a2.x, a3.x, b0.y, b1.y);  // ah*bl
                mma_bf16(acc[f], a0.y, a1.y, a2.y, a3.y, b0.x, b1.x);  // al*bh
                mma_bf16(acc[f], a0.x, a1.x, a2.x, a3.x, b0.x, b1.x);  // ah*bh
            }
        }
        __syncthreads();
    }

    #pragma unroll
    for (int f = 0; f < 8; f++) {
        int c0 = n0 + 8 * f + 2 * t, c1 = c0 + 1;
        if (c0 < N) {
            float bv = bias[c0];
            C[(size_t)(m0 + row0) * N + c0] = fmaxf(acc[f][0] + bv, 0.0f);
            C[(size_t)(m0 + row0 + 8) * N + c0] = fmaxf(acc[f][2] + bv, 0.0f);
        }
        if (c1 < N) {
            float bv = bias[c1];
            C[(size_t)(m0 + row0) * N + c1] = fmaxf(acc[f][1] + bv, 0.0f);
            C[(size_t)(m0 + row0 + 8) * N + c1] = fmaxf(acc[f][3] + bv, 0.0f);
        }
    }
}

// ---------------------------------------------------------------------------
// Prep per graph-conv layer (same as R10/R13).
// ---------------------------------------------------------------------------
template <int C, int C2, int COUT, int VN>
__global__ void gc_prep_kernel(const float* __restrict__ H,
                               const float* __restrict__ Wg,
                               uint4* __restrict__ Kpk4,
                               uint2* __restrict__ Vq,
                               float* __restrict__ ksql_g) {
    constexpr int KW4 = C2 / 2;   // uint4 per node
    __shared__ float Hs[64][C + 1];
    __shared__ float Wgs[C * COUT];
    __shared__ float Vsf[64 * VN];
    const int tid = threadIdx.x;
    const int batch = blockIdx.y;
    const int n0 = blockIdx.x * 64;
    const float* Hb = H + (size_t)batch * NN * C + (size_t)n0 * C;

    for (int idx = tid; idx < 64 * C; idx += 256) {
        Hs[idx / C][idx % C] = Hb[idx];
    }
    for (int idx = tid; idx < C * COUT; idx += 256) Wgs[idx] = Wg[idx];
    __syncthreads();

    uint4* Kb = Kpk4 + (size_t)(batch * NN + n0) * KW4;
    for (int idx = tid; idx < 64 * KW4; idx += 256) {
        int r = idx / KW4, w = idx % KW4;
        int ks = w >> 2, t = w & 3;
        int c2a = 8 * ks + t, c2b = c2a + 4;
        float e0 = (2 * c2a < C) ? Hs[r][2 * c2a] : 0.0f;
        float o0 = (2 * c2a + 1 < C) ? Hs[r][2 * c2a + 1] : 0.0f;
        float e1 = (2 * c2b < C) ? Hs[r][2 * c2b] : 0.0f;
        float o1 = (2 * c2b + 1 < C) ? Hs[r][2 * c2b + 1] : 0.0f;
        uint32_t h0, l0, h1, l1;
        split2(e0, o0, h0, l0);
        split2(e1, o1, h1, l1);
        Kb[idx] = make_uint4(h0, l0, h1, l1);
    }
    if (tid < 64) {
        float s = 0.0f;
        #pragma unroll 4
        for (int c = 0; c < C; c++) { float v = Hs[tid][c]; s += v * v; }
        ksql_g[(size_t)batch * NN + n0 + tid] = s * LOG2E_F;
    }
    for (int idx = tid; idx < 64 * VN; idx += 256) {
        int r = idx / VN, o = idx % VN;
        float v = 0.0f;
        if (o < COUT) {
            #pragma unroll 4
            for (int c = 0; c < C; c++) v += Hs[r][c] * Wgs[c * COUT + o];
        }
        Vsf[r * VN + o] = v;
    }
    __syncthreads();
    uint2* Vb = Vq + (size_t)(batch * (NN / 64) + blockIdx.x) * 16 * VN;
    for (int idx = tid; idx < 16 * VN; idx += 256) {
        int w = idx / VN, c = idx % VN;
        int r0 = (w >> 2) * 8 + (w & 3);   // keypair row in tile
        int r1 = r0 + 4;
        Vb[idx] = make_uint2(
            packbf2(Vsf[(2 * r0) * VN + c], Vsf[(2 * r0 + 1) * VN + c]),
            packbf2(Vsf[(2 * r1) * VN + c], Vsf[(2 * r1 + 1) * VN + c]));
    }
}

// ---------------------------------------------------------------------------
// Wide attention kernel (R13 structure, template MINB): 128 threads = 4
// warps, each warp owns 32 query rows (two m16 row-blocks) -> 128 query rows
// per block.  Full-tile S (16 independent MMA chains), then exp, then P@V.
// Every K LDS.128 feeds 6 MMAs, every V LDS.64 feeds 2 MMAs.
// attn80: MINB=2 (245 regs, measured-best).  attn40: MINB=3 (~165 regs).
// ---------------------------------------------------------------------------
template <int C2, int COUT, int VN, int VP, int MINB>
__global__ __launch_bounds__(128, MINB)
void gc_attn128_kernel(const uint4* __restrict__ Kpk4,
                       const float* __restrict__ ksql_g,
                       const uint2* __restrict__ Vq,
                       const float* __restrict__ bg,
                       float* __restrict__ Out) {
    static_assert(C2 % 8 == 0, "");
    constexpr int KS16 = C2 / 8;
    constexpr int KW4 = C2 / 2;
    constexpr int NT = VN / 8;
    constexpr int KI = 64 * KW4 / 128;
    constexpr int VI = (16 * VN + 127) / 128;
    constexpr int KBUF = 64 * KW4;
    constexpr int VBUF = 16 * VP;
    constexpr int NTILE = NN / 64;

    extern __shared__ char smraw[];
    uint4* Ks = (uint4*)smraw;                       // [2][KBUF]
    uint2* Vs = (uint2*)(Ks + 2 * KBUF);             // [2][VBUF]
    float* ksqs = (float*)(Vs + 2 * VBUF);           // [2][64]

    const int tid = threadIdx.x;
    const int lane = tid & 31, warp = tid >> 5;
    const int g = lane >> 2, t = lane & 3;
    const int batch = blockIdx.y;
    const int q0 = blockIdx.x * 128;
    const uint4* Kg = Kpk4 + (size_t)batch * NN * KW4;
    const uint2* Vg = Vq + (size_t)batch * (NN / 64) * 16 * VN;
    const float* ksqlb = ksql_g + (size_t)batch * NN;

    const int row0 = warp * 32 + g;   // rows row0, +8 (block A), +16, +24 (block B)

    // ---- Q fragments in registers (fragment order) ----
    uint4 qA0[KS16], qA1[KS16], qB0[KS16], qB1[KS16];
    {
        const uint4* Q0 = Kg + (size_t)(q0 + row0) * KW4;
        const uint4* Q1 = Kg + (size_t)(q0 + row0 + 8) * KW4;
        const uint4* Q2 = Kg + (size_t)(q0 + row0 + 16) * KW4;
        const uint4* Q3 = Kg + (size_t)(q0 + row0 + 24) * KW4;
        #pragma unroll
        for (int ks = 0; ks < KS16; ks++) {
            qA0[ks] = Q0[ks * 4 + t];
            qA1[ks] = Q1[ks * 4 + t];
            qB0[ks] = Q2[ks * 4 + t];
            qB1[ks] = Q3[ks * 4 + t];
        }
    }
    const float ql0 = ksqlb[q0 + row0];
    const float ql1 = ksqlb[q0 + row0 + 8];
    const float ql2 = ksqlb[q0 + row0 + 16];
    const float ql3 = ksqlb[q0 + row0 + 24];

    const uint32_t ks_s = (uint32_t)__cvta_generic_to_shared(Ks);
    const uint32_t vs_s = (uint32_t)__cvta_generic_to_shared(Vs);
    const uint32_t kq_s = (uint32_t)__cvta_generic_to_shared(ksqs);

    #define PREFETCH(tile_, buf_)                                              \
    do {                                                                       \
        const int kk0 = (tile_)*64;                                            \
        _Pragma("unroll")                                                      \
        for (int i = 0; i < KI; i++) {                                         \
            int idx = tid + i * 128;                                           \
            cp_async16(ks_s + ((buf_)*KBUF + idx) * 16,                        \
                       &Kg[(size_t)kk0 * KW4 + idx]);                          \
        }                                                                      \
        _Pragma("unroll")                                                      \
        for (int i = 0; i < VI; i++) {                                         \
            int idx = tid + i * 128;                                           \
            if (idx < 16 * VN) {                                               \
                int w = idx / VN, c = idx % VN;                                \
                cp_async8(vs_s + ((buf_)*VBUF + w * VP + c) * 8,               \
                          &Vg[(size_t)(tile_)*16 * VN + idx]);                 \
            }                                                                  \
        }                                                                      \
        if (tid < 64)                                                          \
            cp_async4(kq_s + ((buf_)*64 + tid) * 4, &ksqlb[kk0 + tid]);        \
    } while (0)

    PREFETCH(0, 0);
    cp_commit();

    float accA[NT][4], accB[NT][4];
    #pragma unroll
    for (int j = 0; j < NT; j++) {
        accA[j][0] = accA[j][1] = accA[j][2] = accA[j][3] = 0.0f;
        accB[j][0] = accB[j][1] = accB[j][2] = accB[j][3] = 0.0f;
    }
    float lA0 = 0.0f, lA1 = 0.0f, lB0 = 0.0f, lB1 = 0.0f;

    for (int tile = 0; tile < NTILE; tile++) {
        const int buf = tile & 1;
        if (tile + 1 < NTILE) PREFETCH(tile + 1, buf ^ 1);
        cp_commit();
        cp_wait1();
        __syncthreads();

        const uint4* Kb = Ks + buf * KBUF;
        const uint2* Vt = Vs + buf * VBUF;
        const float* kqt = ksqs + buf * 64;

        // ---- S = Q @ K^T: one LDS.128 per (ks,j) feeds 6 MMAs ----
        float sA[8][4], sB[8][4];
        #pragma unroll
        for (int j = 0; j < 8; j++) {
            sA[j][0] = sA[j][1] = sA[j][2] = sA[j][3] = 0.0f;
            sB[j][0] = sB[j][1] = sB[j][2] = sB[j][3] = 0.0f;
        }
        #pragma unroll
        for (int ks = 0; ks < KS16; ks++) {
            #pragma unroll
            for (int j = 0; j < 8; j++) {
                uint4 kb = Kb[(8 * j + g) * KW4 + ks * 4 + t];
                mma_bf16(sA[j], qA0[ks].x, qA1[ks].x, qA0[ks].z, qA1[ks].z, kb.y, kb.w);
                mma_bf16(sA[j], qA0[ks].y, qA1[ks].y, qA0[ks].w, qA1[ks].w, kb.x, kb.z);
                mma_bf16(sA[j], qA0[ks].x, qA1[ks].x, qA0[ks].z, qA1[ks].z, kb.x, kb.z);
                mma_bf16(sB[j], qB0[ks].x, qB1[ks].x, qB0[ks].z, qB1[ks].z, kb.y, kb.w);
                mma_bf16(sB[j], qB0[ks].y, qB1[ks].y, qB0[ks].w, qB1[ks].w, kb.x, kb.z);
                mma_bf16(sB[j], qB0[ks].x, qB1[ks].x, qB0[ks].z, qB1[ks].z, kb.x, kb.z);
            }
        }

        // ---- p = exp2(2*log2e*s - ksql - qsql); pack as bf16 A-fragments ----
        uint2 pkA[8], pkB[8];
        #pragma unroll
        for (int j = 0; j < 8; j++) {
            float kl0 = kqt[8 * j + 2 * t], kl1 = kqt[8 * j + 2 * t + 1];
            float a00 = ex2f(fmaf(sA[j][0], C2E_F, -(kl0 + ql0)));
            float a01 = ex2f(fmaf(sA[j][1], C2E_F, -(kl1 + ql0)));
            float a02 = ex2f(fmaf(sA[j][2], C2E_F, -(kl0 + ql1)));
            float a03 = ex2f(fmaf(sA[j][3], C2E_F, -(kl1 + ql1)));
            lA0 += a00 + a01;
            lA1 += a02 + a03;
            pkA[j] = make_uint2(packbf2(a00, a01), packbf2(a02, a03));
            float b00 = ex2f(fmaf(sB[j][0], C2E_F, -(kl0 + ql2)));
            float b01 = ex2f(fmaf(sB[j][1], C2E_F, -(kl1 + ql2)));
            float b02 = ex2f(fmaf(sB[j][2], C2E_F, -(kl0 + ql3)));
            float b03 = ex2f(fmaf(sB[j][3], C2E_F, -(kl1 + ql3)));
            lB0 += b00 + b01;
            lB1 += b02 + b03;
            pkB[j] = make_uint2(packbf2(b00, b01), packbf2(b02, b03));
        }

        // ---- O += P @ V: one LDS.64 per (kbp,jj) feeds 2 MMAs ----
        #pragma unroll
        for (int kbp = 0; kbp < 4; kbp++) {
            uint32_t aA0 = pkA[2 * kbp].x, aA1 = pkA[2 * kbp].y;
            uint32_t aA2 = pkA[2 * kbp + 1].x, aA3 = pkA[2 * kbp + 1].y;
            uint32_t aB0 = pkB[2 * kbp].x, aB1 = pkB[2 * kbp].y;
            uint32_t aB2 = pkB[2 * kbp + 1].x, aB3 = pkB[2 * kbp + 1].y;
            #pragma unroll
            for (int jj = 0; jj < NT; jj++) {
                uint2 vv = Vt[(kbp * 4 + t) * VP + 8 * jj + g];
                mma_bf16(accA[jj], aA0, aA1, aA2, aA3, vv.x, vv.y);
                mma_bf16(accB[jj], aB0, aB1, aB2, aB3, vv.x, vv.y);
            }
        }
        __syncthreads();
    }
    #undef PREFETCH

    // ---- epilogue ----
    lA0 += __shfl_xor_sync(0xffffffffu, lA0, 1);
    lA0 += __shfl_xor_sync(0xffffffffu, lA0, 2);
    lA1 += __shfl_xor_sync(0xffffffffu, lA1, 1);
    lA1 += __shfl_xor_sync(0xffffffffu, lA1, 2);
    lB0 += __shfl_xor_sync(0xffffffffu, lB0, 1);
    lB0 += __shfl_xor_sync(0xffffffffu, lB0, 2);
    lB1 += __shfl_xor_sync(0xffffffffu, lB1, 1);
    lB1 += __shfl_xor_sync(0xffffffffu, lB1, 2);
    float iA0 = 1.0f / lA0, iA1 = 1.0f / lA1;
    float iB0 = 1.0f / lB0, iB1 = 1.0f / lB1;
    float* Outb = Out + (size_t)batch * NN * COUT + (size_t)q0 * COUT;
    #pragma unroll
    for (int j = 0; j < NT; j++) {
        int c0 = 8 * j + 2 * t, c1 = c0 + 1;
        if (c0 < COUT) {
            float bv = __ldg(&bg[c0]);
            Outb[row0 * COUT + c0] = fmaxf(accA[j][0] * iA0 + bv, 0.0f);
            Outb[(row0 + 8) * COUT + c0] = fmaxf(accA[j][2] * iA1 + bv, 0.0f);
            Outb[(row0 + 16) * COUT + c0] = fmaxf(accB[j][0] * iB0 + bv, 0.0f);
            Outb[(row0 + 24) * COUT + c0] = fmaxf(accB[j][2] * iB1 + bv, 0.0f);
        }
        if (c1 < COUT) {
            float bv = __ldg(&bg[c1]);
            Outb[row0 * COUT + c1] = fmaxf(accA[j][1] * iA0 + bv, 0.0f);
            Outb[(row0 + 8) * COUT + c1] = fmaxf(accA[j][3] * iA1 + bv, 0.0f);
            Outb[(row0 + 16) * COUT + c1] = fmaxf(accB[j][1] * iB0 + bv, 0.0f);
            Outb[(row0 + 24) * COUT + c1] = fmaxf(accB[j][3] * iB1 + bv, 0.0f);
        }
    }
}

// ---------------------------------------------------------------------------
// Mean over nodes -> classifier -> softmax. One block per batch.
// ---------------------------------------------------------------------------
__global__ void finalize_kernel(const float* __restrict__ H4,
                                const float* __restrict__ Wf,
                                const float* __restrict__ bf,
                                float* __restrict__ out) {
    int b = blockIdx.x;
    int tid = threadIdx.x;
    __shared__ float sred[5][256];
    float local[5] = {};
    const float* Hb = H4 + (long)b * NN * 5;
    for (int r = tid; r < NN; r += 256) {
        #pragma unroll
        for (int c = 0; c < 5; c++) local[c] += Hb[r * 5 + c];
    }
    #pragma unroll
    for (int c = 0; c < 5; c++) sred[c][tid] = local[c];
    __syncthreads();
    for (int s = 128; s > 0; s >>= 1) {
        if (tid < s) {
            #pragma unroll
            for (int c = 0; c < 5; c++) sred[c][tid] += sred[c][tid + s];
        }
        __syncthreads();
    }
    if (tid == 0) {
        float mean[5];
        #pragma unroll
        for (int c = 0; c < 5; c++) mean[c] = sred[c][0] / (float)NN;
        float lg[2];
        #pragma unroll
        for (int o = 0; o < 2; o++) {
            float v = bf[o];
            #pragma unroll
            for (int c = 0; c < 5; c++) v += mean[c] * Wf[c * 2 + o];
            lg[o] = v;
        }
        float mx = fmaxf(lg[0], lg[1]);
        float e0 = expf(lg[0] - mx), e1 = expf(lg[1] - mx);
        float inv = 1.0f / (e0 + e1);
        out[b * 2 + 0] = e0 * inv;
        out[b * 2 + 1] = e1 * inv;
    }
}

// ---------------------------------------------------------------------------

static size_t attn_smem_bytes(int C2, int VP) {
    int kw4 = C2 / 2;
    return (size_t)2 * 64 * kw4 * 16 + (size_t)2 * 16 * VP * 8 + 2 * 64 * 4;
}

extern "C" void kernel_launch(void* const* d_in, const int* in_sizes, int n_in,
                              void* d_out, int out_size) {
    const float* x   = (const float*)d_in[0];
    const float* W1  = (const float*)d_in[1];
    const float* b1  = (const float*)d_in[2];
    const float* W2  = (const float*)d_in[3];
    const float* b2  = (const float*)d_in[4];
    const float* Wg1 = (const float*)d_in[5];
    const float* bg1 = (const float*)d_in[6];
    const float* Wg2 = (const float*)d_in[7];
    const float* bg2 = (const float*)d_in[8];
    const float* Wf  = (const float*)d_in[9];
    const float* bf  = (const float*)d_in[10];
    float* out = (float*)d_out;

    float *h1, *h2, *h3, *h4, *ksql;
    uint4 *k1, *k2;
    uint2 *v1, *v2;
    cudaGetSymbolAddress((void**)&h1, g_h1);
    cudaGetSymbolAddress((void**)&h2, g_h2);
    cudaGetSymbolAddress((void**)&h3, g_h3);
    cudaGetSymbolAddress((void**)&h4, g_h4);
    cudaGetSymbolAddress((void**)&k1, g_kpk1);
    cudaGetSymbolAddress((void**)&k2, g_kpk2);
    cudaGetSymbolAddress((void**)&v1, g_vq1);
    cudaGetSymbolAddress((void**)&v2, g_vq2);
    cudaGetSymbolAddress((void**)&ksql, g_ksql);

    size_t smem1 = attn_smem_bytes(40, 44);
    size_t smem2 = attn_smem_bytes(24, 12);
    cudaFuncSetAttribute(gc_attn128_kernel<40, 40, 40, 44, 2>,
                         cudaFuncAttributeMaxDynamicSharedMemorySize, (int)smem1);
    cudaFuncSetAttribute(gc_attn128_kernel<24, 5, 8, 12, 3>,
                         cudaFuncAttributeMaxDynamicSharedMemorySize, (int)smem2);

    const int M = BQ * NN;  // 65536
    dim3 gprep(NN / 64, BQ);
    dim3 gattn(NN / 128, BQ);

    gemm_mma_relu_kernel<<<dim3(3, M / 128), 256>>>(x, W1, b1, h1, M, 320, 160);
    gemm_mma_relu_kernel<<<dim3(2, M / 128), 256>>>(h1, W2, b2, h2, M, 160, 80);

    gc_prep_kernel<80, 40, 40, 40><<<gprep, 256>>>(h2, Wg1, k1, v1, ksql);
    gc_attn128_kernel<40, 40, 40, 44, 2><<<gattn, 128, smem1>>>(
        k1, ksql, v1, bg1, h3);

    gc_prep_kernel<40, 24, 5, 8><<<gprep, 256>>>(h3, Wg2, k2, v2, ksql);
    gc_attn128_kernel<24, 5, 8, 12, 3><<<gattn, 128, smem2>>>(
        k2, ksql, v2, bg2, h4);

    finalize_kernel<<<BQ, 256>>>(h4, Wf, bf, out);
}

// round 16
// speedup vs baseline: 1.0925x; 1.0260x over previous
#include <cuda_runtime.h>
#include <cuda_bf16.h>
#include <math.h>
#include <stdint.h>

#define BQ 32
#define NN 2048

// Scratch (device globals; no allocations allowed)
__device__ uint4 g_xp[BQ * NN * 80];            // packed x     (C=320 -> 80 uint4/row)
__device__ uint4 g_h1p[BQ * NN * 40];           // packed h1    (C=160 -> 40 uint4/row)
__device__ uint4 g_w1p[160 * 80];               // packed W1 [N=160][K=320/4]
__device__ uint4 g_w2p[80 * 40];                // packed W2 [N=80][K=160/4]
__device__ float g_h2[BQ * NN * 80];
__device__ float g_h3[BQ * NN * 40];
__device__ float g_h4[BQ * NN * 5];
// K in fragment order: [batch][node][ks*4+t] = {hi(b0),lo(b0),hi(b1),lo(b1)}
__device__ uint4 g_kpk1[BQ * NN * 20];          // C2=40 -> 20 uint4/node
__device__ uint4 g_kpk2[BQ * NN * 12];          // C2=24 -> 12 uint4/node
// V in tile+fragment order: [batch][tile][kbp*4+t][col] = {b0,b1} (bf16x2 each)
__device__ uint2 g_vq1[BQ * (NN / 64) * 16 * 40];
__device__ uint2 g_vq2[BQ * (NN / 64) * 16 * 8];
__device__ float g_ksql[BQ * NN];               // |h|^2 * log2(e)

// ---------------------------------------------------------------------------
// helpers
// ---------------------------------------------------------------------------
#define LOG2E_F 1.4426950408889634f
#define C2E_F   2.8853900817779268f   // 2*log2(e)

__device__ __forceinline__ float ex2f(float x) {
    float r;
    asm("ex2.approx.f32 %0, %1;" : "=f"(r) : "f"(x));
    return r;
}

// pack (e -> low16, o -> high16) as bf16x2
__device__ __forceinline__ uint32_t packbf2(float e, float o) {
    uint32_t r;
    asm("cvt.rn.bf16x2.f32 %0, %1, %2;" : "=r"(r) : "f"(o), "f"(e));
    return r;
}

__device__ __forceinline__ void mma_bf16(float c[4], uint32_t a0, uint32_t a1,
                                         uint32_t a2, uint32_t a3,
                                         uint32_t b0, uint32_t b1) {
    asm volatile(
        "mma.sync.aligned.m16n8k16.row.col.f32.bf16.bf16.f32 "
        "{%0,%1,%2,%3}, {%4,%5,%6,%7}, {%8,%9}, {%0,%1,%2,%3};\n"
        : "+f"(c[0]), "+f"(c[1]), "+f"(c[2]), "+f"(c[3])
        : "r"(a0), "r"(a1), "r"(a2), "r"(a3), "r"(b0), "r"(b1));
}

// split (e,o) into bf16 hi pair + bf16 lo (residual) pair
__device__ __forceinline__ void split2(float xe, float xo, uint32_t& hi, uint32_t& lo) {
    float he = __bfloat162float(__float2bfloat16(xe));
    float ho = __bfloat162float(__float2bfloat16(xo));
    hi = packbf2(xe, xo);
    lo = packbf2(xe - he, xo - ho);
}

__device__ __forceinline__ void cp_async16(uint32_t saddr, const void* gptr) {
    asm volatile("cp.async.ca.shared.global [%0], [%1], 16;\n" ::"r"(saddr), "l"(gptr));
}
__device__ __forceinline__ void cp_async8(uint32_t saddr, const void* gptr) {
    asm volatile("cp.async.ca.shared.global [%0], [%1], 8;\n" ::"r"(saddr), "l"(gptr));
}
__device__ __forceinline__ void cp_async4(uint32_t saddr, const void* gptr) {
    asm volatile("cp.async.ca.shared.global [%0], [%1], 4;\n" ::"r"(saddr), "l"(gptr));
}
__device__ __forceinline__ void cp_commit() {
    asm volatile("cp.async.commit_group;\n");
}
__device__ __forceinline__ void cp_wait1() {
    asm volatile("cp.async.wait_group 1;\n");
}

// ---------------------------------------------------------------------------
// Row packer: X [M,C] fp32 -> Xp [M][C/4] uint4 fragment order.
// word (ks*4+t) = {hi(pair 8ks+t), lo, hi(pair 8ks+t+4), lo}; pair c2 = ch 2c2,2c2+1.
// ---------------------------------------------------------------------------
template <int C>
__global__ void pack_rows_kernel(const float* __restrict__ X,
                                 uint4* __restrict__ Xp, int M) {
    constexpr int KW4 = C / 4;
    int idx = blockIdx.x * 256 + threadIdx.x;
    if (idx >= M * KW4) return;
    int row = idx / KW4, w = idx % KW4;
    int ks = w >> 2, t = w & 3;
    int ch = 16 * ks + 2 * t;
    const float* Xr = X + (size_t)row * C;
    uint32_t h0, l0, h1, l1;
    split2(Xr[ch], Xr[ch + 1], h0, l0);
    split2(Xr[ch + 8], Xr[ch + 9], h1, l1);
    Xp[idx] = make_uint4(h0, l0, h1, l1);
}

// W [K,N] fp32 -> Wp [N][K/4] uint4 fragment order (B-operand, col-major frags)
__global__ void pack_w_kernel(const float* __restrict__ W,
                              uint4* __restrict__ Wp, int K, int N) {
    int KW4 = K / 4;
    int idx = blockIdx.x * 256 + threadIdx.x;
    if (idx >= N * KW4) return;
    int n = idx / KW4, w = idx % KW4;
    int ks = w >> 2, t = w & 3;
    int ch = 16 * ks + 2 * t;
    uint32_t h0, l0, h1, l1;
    split2(W[(size_t)ch * N + n], W[(size_t)(ch + 1) * N + n], h0, l0);
    split2(W[(size_t)(ch + 8) * N + n], W[(size_t)(ch + 9) * N + n], h1, l1);
    Wp[idx] = make_uint4(h0, l0, h1, l1);
}

// ---------------------------------------------------------------------------
// Packed-operand GEMM: C = relu(A @ W + b), bf16x2 3-term, tensor-core.
// A packed [M][KW4], W packed [N][KW4]. 128 threads = 4 warps x 32 rows
// (128 rows/block), BN=64, 2 k16-chunks per stage, cp.async double-buffered.
// PACKOUT: write result as packed uint4 rows (for the next packed GEMM).
// smem row stride 12 uint4 (8 used) == 16 banks mod 32 -> conflict-free LDS.128.
// ---------------------------------------------------------------------------
template <int K16, int N, bool PACKOUT, int KW4O>
__global__ __launch_bounds__(128, 3)
void gemm_packed_kernel(const uint4* __restrict__ Ap,
                        const uint4* __restrict__ Wp,
                        const float* __restrict__ bias,
                        float* __restrict__ Cout,
                        uint4* __restrict__ Cpack) {
    constexpr int KW4 = K16 * 4;
    constexpr int NSTAGE = K16 / 2;
    constexpr int AST = 12;              // padded uint4 stride per A row
    constexpr int ABUF = 128 * AST;      // uint4 per A buffer
    constexpr int WBUF = 64 * AST;       // uint4 per W buffer

    extern __shared__ char smraw[];
    uint4* Ab = (uint4*)smraw;           // [2][ABUF]
    uint4* Wb = Ab + 2 * ABUF;           // [2][WBUF]

    const int tid = threadIdx.x;
    const int lane = tid & 31, warp = tid >> 5;
    const int g = lane >> 2, t = lane & 3;
    const int n0 = blockIdx.x * 64;
    const int m0 = blockIdx.y * 128;
    const int row0 = warp * 32 + g;

    const uint32_t ab_s = (uint32_t)__cvta_generic_to_shared(Ab);
    const uint32_t wb_s = (uint32_t)__cvta_generic_to_shared(Wb);

    #define GPREF(s_, buf_)                                                    \
    do {                                                                       \
        _Pragma("unroll")                                                      \
        for (int i = 0; i < 8; i++) {                                          \
            int idx = tid + i * 128;                                           \
            int r = idx >> 3, w = idx & 7;                                     \
            cp_async16(ab_s + ((buf_)*ABUF + r * AST + w) * 16,                \
                       &Ap[(size_t)(m0 + r) * KW4 + 8 * (s_) + w]);            \
        }                                                                      \
        _Pragma("unroll")                                                      \
        for (int i = 0; i < 4; i++) {                                          \
            int idx = tid + i * 128;                                           \
            int n = idx >> 3, w = idx & 7;                                     \
            if (n0 + n < N)                                                    \
                cp_async16(wb_s + ((buf_)*WBUF + n * AST + w) * 16,            \
                           &Wp[(size_t)(n0 + n) * KW4 + 8 * (s_) + w]);        \
        }                                                                      \
    } while (0)

    GPREF(0, 0);
    cp_commit();

    float accA[8][4], accB[8][4];
    #pragma unroll
    for (int f = 0; f < 8; f++) {
        accA[f][0] = accA[f][1] = accA[f][2] = accA[f][3] = 0.0f;
        accB[f][0] = accB[f][1] = accB[f][2] = accB[f][3] = 0.0f;
    }

    for (int s = 0; s < NSTAGE; s++) {
        const int buf = s & 1;
        if (s + 1 < NSTAGE) GPREF(s + 1, buf ^ 1);
        cp_commit();
        cp_wait1();
        __syncthreads();

        const uint4* At = Ab + buf * ABUF;
        const uint4* Wt = Wb + buf * WBUF;

        #pragma unroll
        for (int ks = 0; ks < 2; ks++) {
            uint4 aA0 = At[row0 * AST + ks * 4 + t];
            uint4 aA1 = At[(row0 + 8) * AST + ks * 4 + t];
            uint4 aB0 = At[(row0 + 16) * AST + ks * 4 + t];
            uint4 aB1 = At[(row0 + 24) * AST + ks * 4 + t];
            #pragma unroll
            for (int f = 0; f < 8; f++) {
                uint4 wb = Wt[(8 * f + g) * AST + ks * 4 + t];
                mma_bf16(accA[f], aA0.x, aA1.x, aA0.z, aA1.z, wb.y, wb.w);
                mma_bf16(accA[f], aA0.y, aA1.y, aA0.w, aA1.w, wb.x, wb.z);
                mma_bf16(accA[f], aA0.x, aA1.x, aA0.z, aA1.z, wb.x, wb.z);
                mma_bf16(accB[f], aB0.x, aB1.x, aB0.z, aB1.z, wb.y, wb.w);
                mma_bf16(accB[f], aB0.y, aB1.y, aB0.w, aB1.w, wb.x, wb.z);
                mma_bf16(accB[f], aB0.x, aB1.x, aB0.z, aB1.z, wb.x, wb.z);
            }
        }
        __syncthreads();
    }
    #undef GPREF

    if constexpr (!PACKOUT) {
        #pragma unroll
        for (int f = 0; f < 8; f++) {
            int c0 = n0 + 8 * f + 2 * t, c1 = c0 + 1;
            if (c0 < N) {
                float bv = __ldg(&bias[c0]);
                Cout[(size_t)(m0 + row0) * N + c0] = fmaxf(accA[f][0] + bv, 0.0f);
                Cout[(size_t)(m0 + row0 + 8) * N + c0] = fmaxf(accA[f][2] + bv, 0.0f);
                Cout[(size_t)(m0 + row0 + 16) * N + c0] = fmaxf(accB[f][0] + bv, 0.0f);
                Cout[(size_t)(m0 + row0 + 24) * N + c0] = fmaxf(accB[f][2] + bv, 0.0f);
            }
            if (c1 < N) {
                float bv = __ldg(&bias[c1]);
                Cout[(size_t)(m0 + row0) * N + c1] = fmaxf(accA[f][1] + bv, 0.0f);
                Cout[(size_t)(m0 + row0 + 8) * N + c1] = fmaxf(accA[f][3] + bv, 0.0f);
                Cout[(size_t)(m0 + row0 + 16) * N + c1] = fmaxf(accB[f][1] + bv, 0.0f);
                Cout[(size_t)(m0 + row0 + 24) * N + c1] = fmaxf(accB[f][3] + bv, 0.0f);
            }
        }
    } else {
        // packed output: pair (fe, fe+1) -> one uint4 per row
        #pragma unroll
        for (int fe = 0; fe < 8; fe += 2) {
            if (n0 + 8 * fe + 15 < N) {
                int c0 = n0 + 8 * fe + 2 * t;
                float b0 = __ldg(&bias[c0]);
                float b1 = __ldg(&bias[c0 + 1]);
                float b2 = __ldg(&bias[c0 + 8]);
                float b3 = __ldg(&bias[c0 + 9]);
                int c2 = (n0 >> 1) + 4 * fe + t;
                int word = ((c2 >> 3) << 2) + t;
                #pragma unroll
                for (int rb = 0; rb < 4; rb++) {
                    int row = m0 + row0 + rb * 8;
                    float v0, v1, v2, v3;
                    if (rb == 0) {
                        v0 = accA[fe][0]; v1 = accA[fe][1];
                        v2 = accA[fe + 1][0]; v3 = accA[fe + 1][1];
                    } else if (rb == 1) {
                        v0 = accA[fe][2]; v1 = accA[fe][3];
                        v2 = accA[fe + 1][2]; v3 = accA[fe + 1][3];
                    } else if (rb == 2) {
                        v0 = accB[fe][0]; v1 = accB[fe][1];
                        v2 = accB[fe + 1][0]; v3 = accB[fe + 1][1];
                    } else {
                        v0 = accB[fe][2]; v1 = accB[fe][3];
                        v2 = accB[fe + 1][2]; v3 = accB[fe + 1][3];
                    }
                    v0 = fmaxf(v0 + b0, 0.0f);
                    v1 = fmaxf(v1 + b1, 0.0f);
                    v2 = fmaxf(v2 + b2, 0.0f);
                    v3 = fmaxf(v3 + b3, 0.0f);
                    uint32_t h0, l0, h1, l1;
                    split2(v0, v1, h0, l0);
                    split2(v2, v3, h1, l1);
                    Cpack[(size_t)row * KW4O + word] = make_uint4(h0, l0, h1, l1);
                }
            }
        }
    }
}

// ---------------------------------------------------------------------------
// Prep per graph-conv layer (same as R10/R13).
// ---------------------------------------------------------------------------
template <int C, int C2, int COUT, int VN>
__global__ void gc_prep_kernel(const float* __restrict__ H,
                               const float* __restrict__ Wg,
                               uint4* __restrict__ Kpk4,
                               uint2* __restrict__ Vq,
                               float* __restrict__ ksql_g) {
    constexpr int KW4 = C2 / 2;   // uint4 per node
    __shared__ float Hs[64][C + 1];
    __shared__ float Wgs[C * COUT];
    __shared__ float Vsf[64 * VN];
    const int tid = threadIdx.x;
    const int batch = blockIdx.y;
    const int n0 = blockIdx.x * 64;
    const float* Hb = H + (size_t)batch * NN * C + (size_t)n0 * C;

    for (int idx = tid; idx < 64 * C; idx += 256) {
        Hs[idx / C][idx % C] = Hb[idx];
    }
    for (int idx = tid; idx < C * COUT; idx += 256) Wgs[idx] = Wg[idx];
    __syncthreads();

    uint4* Kb = Kpk4 + (size_t)(batch * NN + n0) * KW4;
    for (int idx = tid; idx < 64 * KW4; idx += 256) {
        int r = idx / KW4, w = idx % KW4;
        int ks = w >> 2, t = w & 3;
        int c2a = 8 * ks + t, c2b = c2a + 4;
        float e0 = (2 * c2a < C) ? Hs[r][2 * c2a] : 0.0f;
        float o0 = (2 * c2a + 1 < C) ? Hs[r][2 * c2a + 1] : 0.0f;
        float e1 = (2 * c2b < C) ? Hs[r][2 * c2b] : 0.0f;
        float o1 = (2 * c2b + 1 < C) ? Hs[r][2 * c2b + 1] : 0.0f;
        uint32_t h0, l0, h1, l1;
        split2(e0, o0, h0, l0);
        split2(e1, o1, h1, l1);
        Kb[idx] = make_uint4(h0, l0, h1, l1);
    }
    if (tid < 64) {
        float s = 0.0f;
        #pragma unroll 4
        for (int c = 0; c < C; c++) { float v = Hs[tid][c]; s += v * v; }
        ksql_g[(size_t)batch * NN + n0 + tid] = s * LOG2E_F;
    }
    for (int idx = tid; idx < 64 * VN; idx += 256) {
        int r = idx / VN, o = idx % VN;
        float v = 0.0f;
        if (o < COUT) {
            #pragma unroll 4
            for (int c = 0; c < C; c++) v += Hs[r][c] * Wgs[c * COUT + o];
        }
        Vsf[r * VN + o] = v;
    }
    __syncthreads();
    uint2* Vb = Vq + (size_t)(batch * (NN / 64) + blockIdx.x) * 16 * VN;
    for (int idx = tid; idx < 16 * VN; idx += 256) {
        int w = idx / VN, c = idx % VN;
        int r0 = (w >> 2) * 8 + (w & 3);   // keypair row in tile
        int r1 = r0 + 4;
        Vb[idx] = make_uint2(
            packbf2(Vsf[(2 * r0) * VN + c], Vsf[(2 * r0 + 1) * VN + c]),
            packbf2(Vsf[(2 * r1) * VN + c], Vsf[(2 * r1 + 1) * VN + c]));
    }
}

// ---------------------------------------------------------------------------
// Wide attention kernel (R13, unchanged): 4 warps x 32 query rows = 128 rows.
// ---------------------------------------------------------------------------
template <int C2, int COUT, int VN, int VP>
__global__ __launch_bounds__(128, 2)
void gc_attn128_kernel(const uint4* __restrict__ Kpk4,
                       const float* __restrict__ ksql_g,
                       const uint2* __restrict__ Vq,
                       const float* __restrict__ bg,
                       float* __restrict__ Out) {
    static_assert(C2 % 8 == 0, "");
    constexpr int KS16 = C2 / 8;
    constexpr int KW4 = C2 / 2;
    constexpr int NT = VN / 8;
    constexpr int KI = 64 * KW4 / 128;
    constexpr int VI = (16 * VN + 127) / 128;
    constexpr int KBUF = 64 * KW4;
    constexpr int VBUF = 16 * VP;
    constexpr int NTILE = NN / 64;

    extern __shared__ char smraw[];
    uint4* Ks = (uint4*)smraw;                       // [2][KBUF]
    uint2* Vs = (uint2*)(Ks + 2 * KBUF);             // [2][VBUF]
    float* ksqs = (float*)(Vs + 2 * VBUF);           // [2][64]

    const int tid = threadIdx.x;
    const int lane = tid & 31, warp = tid >> 5;
    const int g = lane >> 2, t = lane & 3;
    const int batch = blockIdx.y;
    const int q0 = blockIdx.x * 128;
    const uint4* Kg = Kpk4 + (size_t)batch * NN * KW4;
    const uint2* Vg = Vq + (size_t)batch * (NN / 64) * 16 * VN;
    const float* ksqlb = ksql_g + (size_t)batch * NN;

    const int row0 = warp * 32 + g;

    uint4 qA0[KS16], qA1[KS16], qB0[KS16], qB1[KS16];
    {
        const uint4* Q0 = Kg + (size_t)(q0 + row0) * KW4;
        const uint4* Q1 = Kg + (size_t)(q0 + row0 + 8) * KW4;
        const uint4* Q2 = Kg + (size_t)(q0 + row0 + 16) * KW4;
        const uint4* Q3 = Kg + (size_t)(q0 + row0 + 24) * KW4;
        #pragma unroll
        for (int ks = 0; ks < KS16; ks++) {
            qA0[ks] = Q0[ks * 4 + t];
            qA1[ks] = Q1[ks * 4 + t];
            qB0[ks] = Q2[ks * 4 + t];
            qB1[ks] = Q3[ks * 4 + t];
        }
    }
    const float ql0 = ksqlb[q0 + row0];
    const float ql1 = ksqlb[q0 + row0 + 8];
    const float ql2 = ksqlb[q0 + row0 + 16];
    const float ql3 = ksqlb[q0 + row0 + 24];

    const uint32_t ks_s = (uint32_t)__cvta_generic_to_shared(Ks);
    const uint32_t vs_s = (uint32_t)__cvta_generic_to_shared(Vs);
    const uint32_t kq_s = (uint32_t)__cvta_generic_to_shared(ksqs);

    #define PREFETCH(tile_, buf_)                                              \
    do {                                                                       \
        const int kk0 = (tile_)*64;                                            \
        _Pragma("unroll")                                                      \
        for (int i = 0; i < KI; i++) {                                         \
            int idx = tid + i * 128;                                           \
            cp_async16(ks_s + ((buf_)*KBUF + idx) * 16,                        \
                       &Kg[(size_t)kk0 * KW4 + idx]);                          \
        }                                                                      \
        _Pragma("unroll")                                                      \
        for (int i = 0; i < VI; i++) {                                         \
            int idx = tid + i * 128;                                           \
            if (idx < 16 * VN) {                                               \
                int w = idx / VN, c = idx % VN;                                \
                cp_async8(vs_s + ((buf_)*VBUF + w * VP + c) * 8,               \
                          &Vg[(size_t)(tile_)*16 * VN + idx]);                 \
            }                                                                  \
        }                                                                      \
        if (tid < 64)                                                          \
            cp_async4(kq_s + ((buf_)*64 + tid) * 4, &ksqlb[kk0 + tid]);        \
    } while (0)

    PREFETCH(0, 0);
    cp_commit();

    float accA[NT][4], accB[NT][4];
    #pragma unroll
    for (int j = 0; j < NT; j++) {
        accA[j][0] = accA[j][1] = accA[j][2] = accA[j][3] = 0.0f;
        accB[j][0] = accB[j][1] = accB[j][2] = accB[j][3] = 0.0f;
    }
    float lA0 = 0.0f, lA1 = 0.0f, lB0 = 0.0f, lB1 = 0.0f;

    for (int tile = 0; tile < NTILE; tile++) {
        const int buf = tile & 1;
        if (tile + 1 < NTILE) PREFETCH(tile + 1, buf ^ 1);
        cp_commit();
        cp_wait1();
        __syncthreads();

        const uint4* Kb = Ks + buf * KBUF;
        const uint2* Vt = Vs + buf * VBUF;
        const float* kqt = ksqs + buf * 64;

        float sA[8][4], sB[8][4];
        #pragma unroll
        for (int j = 0; j < 8; j++) {
            sA[j][0] = sA[j][1] = sA[j][2] = sA[j][3] = 0.0f;
            sB[j][0] = sB[j][1] = sB[j][2] = sB[j][3] = 0.0f;
        }
        #pragma unroll
        for (int ks = 0; ks < KS16; ks++) {
            #pragma unroll
            for (int j = 0; j < 8; j++) {
                uint4 kb = Kb[(8 * j + g) * KW4 + ks * 4 + t];
                mma_bf16(sA[j], qA0[ks].x, qA1[ks].x, qA0[ks].z, qA1[ks].z, kb.y, kb.w);
                mma_bf16(sA[j], qA0[ks].y, qA1[ks].y, qA0[ks].w, qA1[ks].w, kb.x, kb.z);
                mma_bf16(sA[j], qA0[ks].x, qA1[ks].x, qA0[ks].z, qA1[ks].z, kb.x, kb.z);
                mma_bf16(sB[j], qB0[ks].x, qB1[ks].x, qB0[ks].z, qB1[ks].z, kb.y, kb.w);
                mma_bf16(sB[j], qB0[ks].y, qB1[ks].y, qB0[ks].w, qB1[ks].w, kb.x, kb.z);
                mma_bf16(sB[j], qB0[ks].x, qB1[ks].x, qB0[ks].z, qB1[ks].z, kb.x, kb.z);
            }
        }

        uint2 pkA[8], pkB[8];
        #pragma unroll
        for (int j = 0; j < 8; j++) {
            float kl0 = kqt[8 * j + 2 * t], kl1 = kqt[8 * j + 2 * t + 1];
            float a00 = ex2f(fmaf(sA[j][0], C2E_F, -(kl0 + ql0)));
            float a01 = ex2f(fmaf(sA[j][1], C2E_F, -(kl1 + ql0)));
            float a02 = ex2f(fmaf(sA[j][2], C2E_F, -(kl0 + ql1)));
            float a03 = ex2f(fmaf(sA[j][3], C2E_F, -(kl1 + ql1)));
            lA0 += a00 + a01;
            lA1 += a02 + a03;
            pkA[j] = make_uint2(packbf2(a00, a01), packbf2(a02, a03));
            float b00 = ex2f(fmaf(sB[j][0], C2E_F, -(kl0 + ql2)));
            float b01 = ex2f(fmaf(sB[j][1], C2E_F, -(kl1 + ql2)));
            float b02 = ex2f(fmaf(sB[j][2], C2E_F, -(kl0 + ql3)));
            float b03 = ex2f(fmaf(sB[j][3], C2E_F, -(kl1 + ql3)));
            lB0 += b00 + b01;
            lB1 += b02 + b03;
            pkB[j] = make_uint2(packbf2(b00, b01), packbf2(b02, b03));
        }

        #pragma unroll
        for (int kbp = 0; kbp < 4; kbp++) {
            uint32_t aA0 = pkA[2 * kbp].x, aA1 = pkA[2 * kbp].y;
            uint32_t aA2 = pkA[2 * kbp + 1].x, aA3 = pkA[2 * kbp + 1].y;
            uint32_t aB0 = pkB[2 * kbp].x, aB1 = pkB[2 * kbp].y;
            uint32_t aB2 = pkB[2 * kbp + 1].x, aB3 = pkB[2 * kbp + 1].y;
            #pragma unroll
            for (int jj = 0; jj < NT; jj++) {
                uint2 vv = Vt[(kbp * 4 + t) * VP + 8 * jj + g];
                mma_bf16(accA[jj], aA0, aA1, aA2, aA3, vv.x, vv.y);
                mma_bf16(accB[jj], aB0, aB1, aB2, aB3, vv.x, vv.y);
            }
        }
        __syncthreads();
    }
    #undef PREFETCH

    lA0 += __shfl_xor_sync(0xffffffffu, lA0, 1);
    lA0 += __shfl_xor_sync(0xffffffffu, lA0, 2);
    lA1 += __shfl_xor_sync(0xffffffffu, lA1, 1);
    lA1 += __shfl_xor_sync(0xffffffffu, lA1, 2);
    lB0 += __shfl_xor_sync(0xffffffffu, lB0, 1);
    lB0 += __shfl_xor_sync(0xffffffffu, lB0, 2);
    lB1 += __shfl_xor_sync(0xffffffffu, lB1, 1);
    lB1 += __shfl_xor_sync(0xffffffffu, lB1, 2);
    float iA0 = 1.0f / lA0, iA1 = 1.0f / lA1;
    float iB0 = 1.0f / lB0, iB1 = 1.0f / lB1;
    float* Outb = Out + (size_t)batch * NN * COUT + (size_t)q0 * COUT;
    #pragma unroll
    for (int j = 0; j < NT; j++) {
        int c0 = 8 * j + 2 * t, c1 = c0 + 1;
        if (c0 < COUT) {
            float bv = __ldg(&bg[c0]);
            Outb[row0 * COUT + c0] = fmaxf(accA[j][0] * iA0 + bv, 0.0f);
            Outb[(row0 + 8) * COUT + c0] = fmaxf(accA[j][2] * iA1 + bv, 0.0f);
            Outb[(row0 + 16) * COUT + c0] = fmaxf(accB[j][0] * iB0 + bv, 0.0f);
            Outb[(row0 + 24) * COUT + c0] = fmaxf(accB[j][2] * iB1 + bv, 0.0f);
        }
        if (c1 < COUT) {
            float bv = __ldg(&bg[c1]);
            Outb[row0 * COUT + c1] = fmaxf(accA[j][1] * iA0 + bv, 0.0f);
            Outb[(row0 + 8) * COUT + c1] = fmaxf(accA[j][3] * iA1 + bv, 0.0f);
            Outb[(row0 + 16) * COUT + c1] = fmaxf(accB[j][1] * iB0 + bv, 0.0f);
            Outb[(row0 + 24) * COUT + c1] = fmaxf(accB[j][3] * iB1 + bv, 0.0f);
        }
    }
}

// ---------------------------------------------------------------------------
// Narrow attention kernel (R10/R13, unchanged): 64 query rows, 16/warp.
// ---------------------------------------------------------------------------
template <int C2, int COUT, int VN, int VP>
__global__ __launch_bounds__(128, 4)
void gc_attn_kernel(const uint4* __restrict__ Kpk4,
                    const float* __restrict__ ksql_g,
                    const uint2* __restrict__ Vq,
                    const float* __restrict__ bg,
                    float* __restrict__ Out) {
    static_assert(C2 % 8 == 0, "");
    constexpr int KS16 = C2 / 8;
    constexpr int KW4 = C2 / 2;
    constexpr int NT = VN / 8;
    constexpr int KI = 64 * KW4 / 128;
    constexpr int VI = (16 * VN + 127) / 128;
    constexpr int KBUF = 64 * KW4;
    constexpr int VBUF = 16 * VP;
    constexpr int NTILE = NN / 64;

    extern __shared__ char smraw[];
    uint4* Ks = (uint4*)smraw;
    uint2* Vs = (uint2*)(Ks + 2 * KBUF);
    float* ksqs = (float*)(Vs + 2 * VBUF);

    const int tid = threadIdx.x;
    const int lane = tid & 31, warp = tid >> 5;
    const int g = lane >> 2, t = lane & 3;
    const int batch = blockIdx.y;
    const int q0 = blockIdx.x * 64;
    const uint4* Kg = Kpk4 + (size_t)batch * NN * KW4;
    const uint2* Vg = Vq + (size_t)batch * (NN / 64) * 16 * VN;
    const float* ksqlb = ksql_g + (size_t)batch * NN;

    const int row0 = warp * 16 + g;

    uint4 qr0[KS16], qr1[KS16];
    {
        const uint4* Q0 = Kg + (size_t)(q0 + row0) * KW4;
        const uint4* Q1 = Kg + (size_t)(q0 + row0 + 8) * KW4;
        #pragma unroll
        for (int ks = 0; ks < KS16; ks++) {
            qr0[ks] = Q0[ks * 4 + t];
            qr1[ks] = Q1[ks * 4 + t];
        }
    }
    const float ql0 = ksqlb[q0 + row0];
    const float ql1 = ksqlb[q0 + row0 + 8];

    const uint32_t ks_s = (uint32_t)__cvta_generic_to_shared(Ks);
    const uint32_t vs_s = (uint32_t)__cvta_generic_to_shared(Vs);
    const uint32_t kq_s = (uint32_t)__cvta_generic_to_shared(ksqs);

    #define PREFETCH(tile_, buf_)                                              \
    do {                                                                       \
        const int kk0 = (tile_)*64;                                            \
        _Pragma("unroll")                                                      \
        for (int i = 0; i < KI; i++) {                                         \
            int idx = tid + i * 128;                                           \
            cp_async16(ks_s + ((buf_)*KBUF + idx) * 16,                        \
                       &Kg[(size_t)kk0 * KW4 + idx]);                          \
        }                                                                      \
        _Pragma("unroll")                                                      \
        for (int i = 0; i < VI; i++) {                                         \
            int idx = tid + i * 128;                                           \
            if (idx < 16 * VN) {                                               \
                int w = idx / VN, c = idx % VN;                                \
                cp_async8(vs_s + ((buf_)*VBUF + w * VP + c) * 8,               \
                          &Vg[(size_t)(tile_)*16 * VN + idx]);                 \
            }                                                                  \
        }                                                                      \
        if (tid < 64)                                                          \
            cp_async4(kq_s + ((buf_)*64 + tid) * 4, &ksqlb[kk0 + tid]);        \
    } while (0)

    PREFETCH(0, 0);
    cp_commit();

    float acc[NT][4];
    #pragma unroll
    for (int j = 0; j < NT; j++)
        acc[j][0] = acc[j][1] = acc[j][2] = acc[j][3] = 0.0f;
    float l0r = 0.0f, l1r = 0.0f;

    for (int tile = 0; tile < NTILE; tile++) {
        const int buf = tile & 1;
        if (tile + 1 < NTILE) PREFETCH(tile + 1, buf ^ 1);
        cp_commit();
        cp_wait1();
        __syncthreads();

        const uint4* Kb = Ks + buf * KBUF;
        const uint2* Vt = Vs + buf * VBUF;
        const float* kqt = ksqs + buf * 64;

        float s[8][4];
        #pragma unroll
        for (int j = 0; j < 8; j++) s[j][0] = s[j][1] = s[j][2] = s[j][3] = 0.0f;

        #pragma unroll
        for (int ks = 0; ks < KS16; ks++) {
            #pragma unroll
            for (int j = 0; j < 8; j++) {
                uint4 kb = Kb[(8 * j + g) * KW4 + ks * 4 + t];
                mma_bf16(s[j], qr0[ks].x, qr1[ks].x, qr0[ks].z, qr1[ks].z, kb.y, kb.w);
                mma_bf16(s[j], qr0[ks].y, qr1[ks].y, qr0[ks].w, qr1[ks].w, kb.x, kb.z);
                mma_bf16(s[j], qr0[ks].x, qr1[ks].x, qr0[ks].z, qr1[ks].z, kb.x, kb.z);
            }
        }

        uint32_t pA[8], pB[8];
        #pragma unroll
        for (int j = 0; j < 8; j++) {
            float kl0 = kqt[8 * j + 2 * t], kl1 = kqt[8 * j + 2 * t + 1];
            float p00 = ex2f(fmaf(s[j][0], C2E_F, -(kl0 + ql0)));
            float p01 = ex2f(fmaf(s[j][1], C2E_F, -(kl1 + ql0)));
            float p10 = ex2f(fmaf(s[j][2], C2E_F, -(kl0 + ql1)));
            float p11 = ex2f(fmaf(s[j][3], C2E_F, -(kl1 + ql1)));
            l0r += p00 + p01;
            l1r += p10 + p11;
            pA[j] = packbf2(p00, p01);
            pB[j] = packbf2(p10, p11);
        }

        #pragma unroll
        for (int kbp = 0; kbp < 4; kbp++) {
            uint32_t a0 = pA[2 * kbp], a1 = pB[2 * kbp];
            uint32_t a2 = pA[2 * kbp + 1], a3 = pB[2 * kbp + 1];
            #pragma unroll
            for (int jj = 0; jj < NT; jj++) {
                uint2 vv = Vt[(kbp * 4 + t) * VP + 8 * jj + g];
                mma_bf16(acc[jj], a0, a1, a2, a3, vv.x, vv.y);
            }
        }
        __syncthreads();
    }
    #undef PREFETCH

    l0r += __shfl_xor_sync(0xffffffffu, l0r, 1);
    l0r += __shfl_xor_sync(0xffffffffu, l0r, 2);
    l1r += __shfl_xor_sync(0xffffffffu, l1r, 1);
    l1r += __shfl_xor_sync(0xffffffffu, l1r, 2);
    float inv0 = 1.0f / l0r, inv1 = 1.0f / l1r;
    float* Outb = Out + (size_t)batch * NN * COUT + (size_t)q0 * COUT;
    #pragma unroll
    for (int j = 0; j < NT; j++) {
        int c0 = 8 * j + 2 * t, c1 = c0 + 1;
        if (c0 < COUT) {
            float b0v = __ldg(&bg[c0]);
            Outb[row0 * COUT + c0] = fmaxf(acc[j][0] * inv0 + b0v, 0.0f);
            Outb[(row0 + 8) * COUT + c0] = fmaxf(acc[j][2] * inv1 + b0v, 0.0f);
        }
        if (c1 < COUT) {
            float b1v = __ldg(&bg[c1]);
            Outb[row0 * COUT + c1] = fmaxf(acc[j][1] * inv0 + b1v, 0.0f);
            Outb[(row0 + 8) * COUT + c1] = fmaxf(acc[j][3] * inv1 + b1v, 0.0f);
        }
    }
}

// ---------------------------------------------------------------------------
// Mean over nodes -> classifier -> softmax. One block per batch.
// ---------------------------------------------------------------------------
__global__ void finalize_kernel(const float* __restrict__ H4,
                                const float* __restrict__ Wf,
                                const float* __restrict__ bf,
                                float* __restrict__ out) {
    int b = blockIdx.x;
    int tid = threadIdx.x;
    __shared__ float sred[5][256];
    float local[5] = {};
    const float* Hb = H4 + (long)b * NN * 5;
    for (int r = tid; r < NN; r += 256) {
        #pragma unroll
        for (int c = 0; c < 5; c++) local[c] += Hb[r * 5 + c];
    }
    #pragma unroll
    for (int c = 0; c < 5; c++) sred[c][tid] = local[c];
    __syncthreads();
    for (int s = 128; s > 0; s >>= 1) {
        if (tid < s) {
            #pragma unroll
            for (int c = 0; c < 5; c++) sred[c][tid] += sred[c][tid + s];
        }
        __syncthreads();
    }
    if (tid == 0) {
        float mean[5];
        #pragma unroll
        for (int c = 0; c < 5; c++) mean[c] = sred[c][0] / (float)NN;
        float lg[2];
        #pragma unroll
        for (int o = 0; o < 2; o++) {
            float v = bf[o];
            #pragma unroll
            for (int c = 0; c < 5; c++) v += mean[c] * Wf[c * 2 + o];
            lg[o] = v;
        }
        float mx = fmaxf(lg[0], lg[1]);
        float e0 = expf(lg[0] - mx), e1 = expf(lg[1] - mx);
        float inv = 1.0f / (e0 + e1);
        out[b * 2 + 0] = e0 * inv;
        out[b * 2 + 1] = e1 * inv;
    }
}

// ---------------------------------------------------------------------------

static size_t attn_smem_bytes(int C2, int VP) {
    int kw4 = C2 / 2;
    return (size_t)2 * 64 * kw4 * 16 + (size_t)2 * 16 * VP * 8 + 2 * 64 * 4;
}

static size_t gemm_smem_bytes() {
    return (size_t)2 * 128 * 12 * 16 + (size_t)2 * 64 * 12 * 16;  // 73728
}

extern "C" void kernel_launch(void* const* d_in, const int* in_sizes, int n_in,
                              void* d_out, int out_size) {
    const float* x   = (const float*)d_in[0];
    const float* W1  = (const float*)d_in[1];
    const float* b1  = (const float*)d_in[2];
    const float* W2  = (const float*)d_in[3];
    const float* b2  = (const float*)d_in[4];
    const float* Wg1 = (const float*)d_in[5];
    const float* bg1 = (const float*)d_in[6];
    const float* Wg2 = (const float*)d_in[7];
    const float* bg2 = (const float*)d_in[8];
    const float* Wf  = (const float*)d_in[9];
    const float* bf  = (const float*)d_in[10];
    float* out = (float*)d_out;

    float *h2, *h3, *h4, *ksql;
    uint4 *xp, *h1p, *w1p, *w2p, *k1, *k2;
    uint2 *v1, *v2;
    cudaGetSymbolAddress((void**)&xp, g_xp);
    cudaGetSymbolAddress((void**)&h1p, g_h1p);
    cudaGetSymbolAddress((void**)&w1p, g_w1p);
    cudaGetSymbolAddress((void**)&w2p, g_w2p);
    cudaGetSymbolAddress((void**)&h2, g_h2);
    cudaGetSymbolAddress((void**)&h3, g_h3);
    cudaGetSymbolAddress((void**)&h4, g_h4);
    cudaGetSymbolAddress((void**)&k1, g_kpk1);
    cudaGetSymbolAddress((void**)&k2, g_kpk2);
    cudaGetSymbolAddress((void**)&v1, g_vq1);
    cudaGetSymbolAddress((void**)&v2, g_vq2);
    cudaGetSymbolAddress((void**)&ksql, g_ksql);

    size_t smem1 = attn_smem_bytes(40, 44);
    size_t smem2 = attn_smem_bytes(24, 12);
    size_t smemg = gemm_smem_bytes();
    cudaFuncSetAttribute(gc_attn128_kernel<40, 40, 40, 44>,
                         cudaFuncAttributeMaxDynamicSharedMemorySize, (int)smem1);
    cudaFuncSetAttribute(gc_attn_kernel<24, 5, 8, 12>,
                         cudaFuncAttributeMaxDynamicSharedMemorySize, (int)smem2);
    cudaFuncSetAttribute(gemm_packed_kernel<20, 160, true, 40>,
                         cudaFuncAttributeMaxDynamicSharedMemorySize, (int)smemg);
    cudaFuncSetAttribute(gemm_packed_kernel<10, 80, false, 1>,
                         cudaFuncAttributeMaxDynamicSharedMemorySize, (int)smemg);

    const int M = BQ * NN;  // 65536
    dim3 gprep(NN / 64, BQ);

    // pack inputs (one-time layout transforms)
    pack_rows_kernel<320><<<(M * 80 + 255) / 256, 256>>>(x, xp, M);
    pack_w_kernel<<<(160 * 80 + 255) / 256, 256>>>(W1, w1p, 320, 160);
    pack_w_kernel<<<(80 * 40 + 255) / 256, 256>>>(W2, w2p, 160, 80);

    // MLP: packed-operand tensor-core GEMMs; gemm1 emits packed h1 directly
    gemm_packed_kernel<20, 160, true, 40><<<dim3(3, M / 128), 128, smemg>>>(
        xp, w1p, b1, nullptr, h1p);
    gemm_packed_kernel<10, 80, false, 1><<<dim3(2, M / 128), 128, smemg>>>(
        h1p, w2p, b2, h2, nullptr);

    gc_prep_kernel<80, 40, 40, 40><<<gprep, 256>>>(h2, Wg1, k1, v1, ksql);
    gc_attn128_kernel<40, 40, 40, 44><<<dim3(NN / 128, BQ), 128, smem1>>>(
        k1, ksql, v1, bg1, h3);

    gc_prep_kernel<40, 24, 5, 8><<<gprep, 256>>>(h3, Wg2, k2, v2, ksql);
    gc_attn_kernel<24, 5, 8, 12><<<dim3(NN / 64, BQ), 128, smem2>>>(
        k2, ksql, v2, bg2, h4);

    finalize_kernel<<<BQ, 256>>>(h4, Wf, bf, out);
}